// round 3
// baseline (speedup 1.0000x reference)
#include <cuda_runtime.h>
#include <math.h>

#define N_NODES 50000
#define IN_F    256
#define OUT_F   64
#define N_EDGES 1600000
#define ALPHA   0.2f

typedef unsigned long long ull;

// ---------------- scratch (static device globals; no allocation) ----------------
__device__ __align__(16) float g_h[(size_t)N_NODES * OUT_F];   // 12.8 MB
__device__ float g_s1[N_NODES];
__device__ float g_s2[N_NODES];
__device__ int   g_count[N_NODES];
__device__ int   g_cursor[N_NODES];
__device__ int   g_rowstart[N_NODES + 1];
__device__ __align__(16) ull g_csr[N_EDGES];                   // 12.8 MB: packed (dst, w)

// ---------------- kernel 0: zero histogram ----------------
__global__ void k_init() {
    int idx = blockIdx.x * blockDim.x + threadIdx.x;
    if (idx < N_NODES) g_count[idx] = 0;
}

// ---------------- kernel 1: h = x @ W ----------------
__global__ __launch_bounds__(256) void k_gemm(const float* __restrict__ x,
                                              const float* __restrict__ W) {
    __shared__ __align__(16) float xs[32 * IN_F];  // 32 KB
    const int tid = threadIdx.x;
    const int nodeBase = blockIdx.x * 32;

    for (int i = tid; i < 32 * IN_F / 4; i += 256) {
        int row  = i >> 6;
        int node = nodeBase + row;
        float4 v = make_float4(0.f, 0.f, 0.f, 0.f);
        if (node < N_NODES)
            v = ((const float4*)(x + (size_t)node * IN_F))[i & 63];
        ((float4*)xs)[i] = v;
    }
    __syncthreads();

    const int f = tid & 63;
    const int g = tid >> 6;
    float acc[8] = {0.f, 0.f, 0.f, 0.f, 0.f, 0.f, 0.f, 0.f};

    #pragma unroll 4
    for (int k0 = 0; k0 < IN_F; k0 += 4) {
        float w0 = W[(k0 + 0) * OUT_F + f];
        float w1 = W[(k0 + 1) * OUT_F + f];
        float w2 = W[(k0 + 2) * OUT_F + f];
        float w3 = W[(k0 + 3) * OUT_F + f];
        #pragma unroll
        for (int j = 0; j < 8; j++) {
            const float4 xv = *(const float4*)&xs[(g * 8 + j) * IN_F + k0];
            acc[j] = fmaf(xv.x, w0, acc[j]);
            acc[j] = fmaf(xv.y, w1, acc[j]);
            acc[j] = fmaf(xv.z, w2, acc[j]);
            acc[j] = fmaf(xv.w, w3, acc[j]);
        }
    }

    #pragma unroll
    for (int j = 0; j < 8; j++) {
        int node = nodeBase + g * 8 + j;
        if (node < N_NODES) g_h[(size_t)node * OUT_F + f] = acc[j];
    }
}

// ---------------- kernel 2: s1 = h@a1, s2 = h@a2 (one warp per node) ----------------
__global__ __launch_bounds__(128) void k_scores(const float* __restrict__ a) {
    int warp = (blockIdx.x * blockDim.x + threadIdx.x) >> 5;
    int lane = threadIdx.x & 31;
    if (warp >= N_NODES) return;
    float h0 = g_h[(size_t)warp * OUT_F + lane];
    float h1 = g_h[(size_t)warp * OUT_F + 32 + lane];
    float p1 = h0 * a[lane]      + h1 * a[lane + 32];
    float p2 = h0 * a[64 + lane] + h1 * a[96 + lane];
    #pragma unroll
    for (int o = 16; o; o >>= 1) {
        p1 += __shfl_xor_sync(0xFFFFFFFFu, p1, o);
        p2 += __shfl_xor_sync(0xFFFFFFFFu, p2, o);
    }
    if (lane == 0) { g_s1[warp] = p1; g_s2[warp] = p2; }
}

// ---------------- kernel 3: histogram of src ----------------
__global__ __launch_bounds__(256) void k_hist(const int* __restrict__ ei) {
    int e = blockIdx.x * blockDim.x + threadIdx.x;
    if (e >= N_EDGES) return;
    atomicAdd(&g_count[ei[e]], 1);
}

// ---------------- kernel 4: single-block scan -> row_start, cursor ----------------
__global__ __launch_bounds__(1024) void k_scan() {
    __shared__ int sh[1024];
    const int t = threadIdx.x;
    const int CH = (N_NODES + 1023) / 1024;  // 49
    int beg = t * CH;
    int end = beg + CH; if (end > N_NODES) end = N_NODES;

    int sum = 0;
    for (int i = beg; i < end; i++) sum += g_count[i];
    sh[t] = sum;
    __syncthreads();

    // inclusive Hillis-Steele scan over 1024 partials
    for (int o = 1; o < 1024; o <<= 1) {
        int v = 0;
        if (t >= o) v = sh[t - o];
        __syncthreads();
        if (t >= o) sh[t] += v;
        __syncthreads();
    }

    int run = (t == 0) ? 0 : sh[t - 1];
    for (int i = beg; i < end; i++) {
        g_rowstart[i] = run;
        g_cursor[i]   = run;
        run += g_count[i];
    }
    if (t == 1023) g_rowstart[N_NODES] = N_EDGES;
}

// ---------------- kernel 5: build CSR with packed (dst, w) ----------------
__global__ __launch_bounds__(256) void k_csr(const int* __restrict__ ei) {
    int e = blockIdx.x * blockDim.x + threadIdx.x;
    if (e >= N_EDGES) return;
    int src = ei[e];
    int dst = ei[N_EDGES + e];
    float s  = g_s1[src] + g_s2[dst];
    float lr = s > 0.f ? s : ALPHA * s;
    float w  = expf(-lr);
    int pos = atomicAdd(&g_cursor[src], 1);
    g_csr[pos] = (ull)(unsigned)dst | ((ull)__float_as_uint(w) << 32);
}

// ---------------- kernel 6: gather per node, fused divide+ELU ----------------
__global__ __launch_bounds__(256) void k_gather(float* __restrict__ out) {
    int warp = (blockIdx.x * blockDim.x + threadIdx.x) >> 5;
    int lane = threadIdx.x & 31;
    if (warp >= N_NODES) return;

    int s = g_rowstart[warp];
    int e = g_rowstart[warp + 1];

    float ax = 0.f, ay = 0.f, rs = 0.f;
    int i = s;
    for (; i + 4 <= e; i += 4) {
        ull v0 = g_csr[i + 0];
        ull v1 = g_csr[i + 1];
        ull v2 = g_csr[i + 2];
        ull v3 = g_csr[i + 3];
        int   d0 = (int)(unsigned)v0;  float w0 = __uint_as_float((unsigned)(v0 >> 32));
        int   d1 = (int)(unsigned)v1;  float w1 = __uint_as_float((unsigned)(v1 >> 32));
        int   d2 = (int)(unsigned)v2;  float w2 = __uint_as_float((unsigned)(v2 >> 32));
        int   d3 = (int)(unsigned)v3;  float w3 = __uint_as_float((unsigned)(v3 >> 32));
        float2 h0 = ((const float2*)(g_h + (size_t)d0 * OUT_F))[lane];
        float2 h1 = ((const float2*)(g_h + (size_t)d1 * OUT_F))[lane];
        float2 h2 = ((const float2*)(g_h + (size_t)d2 * OUT_F))[lane];
        float2 h3 = ((const float2*)(g_h + (size_t)d3 * OUT_F))[lane];
        rs += (w0 + w1) + (w2 + w3);
        ax = fmaf(w0, h0.x, ax); ay = fmaf(w0, h0.y, ay);
        ax = fmaf(w1, h1.x, ax); ay = fmaf(w1, h1.y, ay);
        ax = fmaf(w2, h2.x, ax); ay = fmaf(w2, h2.y, ay);
        ax = fmaf(w3, h3.x, ax); ay = fmaf(w3, h3.y, ay);
    }
    for (; i < e; i++) {
        ull v = g_csr[i];
        int   d = (int)(unsigned)v;
        float w = __uint_as_float((unsigned)(v >> 32));
        float2 h = ((const float2*)(g_h + (size_t)d * OUT_F))[lane];
        rs += w;
        ax = fmaf(w, h.x, ax); ay = fmaf(w, h.y, ay);
    }

    float inv = 1.f / rs;
    float vx = ax * inv;
    float vy = ay * inv;
    vx = vx > 0.f ? vx : expm1f(vx);
    vy = vy > 0.f ? vy : expm1f(vy);
    ((float2*)(out + (size_t)warp * OUT_F))[lane] = make_float2(vx, vy);
}

// ---------------- launch ----------------
extern "C" void kernel_launch(void* const* d_in, const int* in_sizes, int n_in,
                              void* d_out, int out_size) {
    const float* x  = (const float*)d_in[0];
    const float* W  = (const float*)d_in[1];
    const float* a  = (const float*)d_in[2];
    const int*   ei = (const int*)d_in[3];
    float* out = (float*)d_out;

    (void)in_sizes; (void)n_in; (void)out_size;

    k_init<<<(N_NODES + 255) / 256, 256>>>();
    k_gemm<<<(N_NODES + 31) / 32, 256>>>(x, W);
    k_scores<<<(N_NODES * 32 + 127) / 128, 128>>>(a);
    k_hist<<<(N_EDGES + 255) / 256, 256>>>(ei);
    k_scan<<<1, 1024>>>();
    k_csr<<<(N_EDGES + 255) / 256, 256>>>(ei);
    k_gather<<<(N_NODES * 32 + 255) / 256, 256>>>(out);
}

// round 4
// speedup vs baseline: 1.4359x; 1.4359x over previous
#include <cuda_runtime.h>
#include <math.h>

#define N_NODES 50000
#define IN_F    256
#define OUT_F   64
#define N_EDGES 1600000
#define ALPHA   0.2f

#define SCAN_BLOCKS 196   // 196*256 = 50176 >= 50000

typedef unsigned long long ull;

// ---------------- scratch (static device globals; no allocation) ----------------
__device__ __align__(16) float g_h[(size_t)N_NODES * OUT_F];   // 12.8 MB
__device__ float g_s1[N_NODES];
__device__ float g_s2[N_NODES];
__device__ int   g_count[N_NODES];
__device__ int   g_cursor[N_NODES];
__device__ int   g_rowstart[N_NODES + 1];
__device__ int   g_blocksum[SCAN_BLOCKS];
__device__ int   g_blockoff[SCAN_BLOCKS];
__device__ __align__(16) ull g_csr[N_EDGES];                   // 12.8 MB packed (dst, w)

// ---------------- zero histogram ----------------
__global__ void k_init() {
    int idx = blockIdx.x * blockDim.x + threadIdx.x;
    if (idx < N_NODES) g_count[idx] = 0;
}

// ---------------- histogram of src (int4 loads, 4 edges/thread) ----------------
__global__ __launch_bounds__(256) void k_hist(const int* __restrict__ ei) {
    int t = blockIdx.x * blockDim.x + threadIdx.x;
    if (t >= N_EDGES / 4) return;
    int4 v = ((const int4*)ei)[t];
    atomicAdd(&g_count[v.x], 1);
    atomicAdd(&g_count[v.y], 1);
    atomicAdd(&g_count[v.z], 1);
    atomicAdd(&g_count[v.w], 1);
}

// ---------------- scan stage A: per-block sums ----------------
__global__ __launch_bounds__(256) void k_scan_a() {
    __shared__ int sh[256];
    int i = blockIdx.x * 256 + threadIdx.x;
    sh[threadIdx.x] = (i < N_NODES) ? g_count[i] : 0;
    __syncthreads();
    for (int o = 128; o > 0; o >>= 1) {
        if (threadIdx.x < o) sh[threadIdx.x] += sh[threadIdx.x + o];
        __syncthreads();
    }
    if (threadIdx.x == 0) g_blocksum[blockIdx.x] = sh[0];
}

// ---------------- scan stage B: scan of 196 block sums ----------------
__global__ __launch_bounds__(256) void k_scan_b() {
    __shared__ int sh[256];
    int t = threadIdx.x;
    sh[t] = (t < SCAN_BLOCKS) ? g_blocksum[t] : 0;
    __syncthreads();
    #pragma unroll
    for (int o = 1; o < 256; o <<= 1) {
        int v = 0;
        if (t >= o) v = sh[t - o];
        __syncthreads();
        sh[t] += v;
        __syncthreads();
    }
    if (t < SCAN_BLOCKS) g_blockoff[t] = (t == 0) ? 0 : sh[t - 1];
    if (t == 0) g_rowstart[N_NODES] = N_EDGES;
}

// ---------------- scan stage C: block-local exclusive scan + offset ----------------
__global__ __launch_bounds__(256) void k_scan_c() {
    __shared__ int sh[256];
    int t = threadIdx.x;
    int i = blockIdx.x * 256 + t;
    int cnt = (i < N_NODES) ? g_count[i] : 0;
    sh[t] = cnt;
    __syncthreads();
    #pragma unroll
    for (int o = 1; o < 256; o <<= 1) {
        int v = 0;
        if (t >= o) v = sh[t - o];
        __syncthreads();
        sh[t] += v;
        __syncthreads();
    }
    if (i < N_NODES) {
        int excl = g_blockoff[blockIdx.x] + sh[t] - cnt;
        g_rowstart[i] = excl;
        g_cursor[i]   = excl;
    }
}

// ---------------- h = x @ W ----------------
__global__ __launch_bounds__(256) void k_gemm(const float* __restrict__ x,
                                              const float* __restrict__ W) {
    __shared__ __align__(16) float xs[32 * IN_F];  // 32 KB
    const int tid = threadIdx.x;
    const int nodeBase = blockIdx.x * 32;

    for (int i = tid; i < 32 * IN_F / 4; i += 256) {
        int row  = i >> 6;
        int node = nodeBase + row;
        float4 v = make_float4(0.f, 0.f, 0.f, 0.f);
        if (node < N_NODES)
            v = ((const float4*)(x + (size_t)node * IN_F))[i & 63];
        ((float4*)xs)[i] = v;
    }
    __syncthreads();

    const int f = tid & 63;
    const int g = tid >> 6;
    float acc[8] = {0.f, 0.f, 0.f, 0.f, 0.f, 0.f, 0.f, 0.f};

    #pragma unroll 4
    for (int k0 = 0; k0 < IN_F; k0 += 4) {
        float w0 = W[(k0 + 0) * OUT_F + f];
        float w1 = W[(k0 + 1) * OUT_F + f];
        float w2 = W[(k0 + 2) * OUT_F + f];
        float w3 = W[(k0 + 3) * OUT_F + f];
        #pragma unroll
        for (int j = 0; j < 8; j++) {
            const float4 xv = *(const float4*)&xs[(g * 8 + j) * IN_F + k0];
            acc[j] = fmaf(xv.x, w0, acc[j]);
            acc[j] = fmaf(xv.y, w1, acc[j]);
            acc[j] = fmaf(xv.z, w2, acc[j]);
            acc[j] = fmaf(xv.w, w3, acc[j]);
        }
    }

    #pragma unroll
    for (int j = 0; j < 8; j++) {
        int node = nodeBase + g * 8 + j;
        if (node < N_NODES) g_h[(size_t)node * OUT_F + f] = acc[j];
    }
}

// ---------------- s1 = h@a1, s2 = h@a2 (one warp per node) ----------------
__global__ __launch_bounds__(128) void k_scores(const float* __restrict__ a) {
    int warp = (blockIdx.x * blockDim.x + threadIdx.x) >> 5;
    int lane = threadIdx.x & 31;
    if (warp >= N_NODES) return;
    float h0 = g_h[(size_t)warp * OUT_F + lane];
    float h1 = g_h[(size_t)warp * OUT_F + 32 + lane];
    float p1 = h0 * a[lane]      + h1 * a[lane + 32];
    float p2 = h0 * a[64 + lane] + h1 * a[96 + lane];
    #pragma unroll
    for (int o = 16; o; o >>= 1) {
        p1 += __shfl_xor_sync(0xFFFFFFFFu, p1, o);
        p2 += __shfl_xor_sync(0xFFFFFFFFu, p2, o);
    }
    if (lane == 0) { g_s1[warp] = p1; g_s2[warp] = p2; }
}

// ---------------- build CSR with packed (dst, w) ----------------
__global__ __launch_bounds__(256) void k_csr(const int* __restrict__ ei) {
    int e = blockIdx.x * blockDim.x + threadIdx.x;
    if (e >= N_EDGES) return;
    int src = ei[e];
    int dst = ei[N_EDGES + e];
    float s  = g_s1[src] + g_s2[dst];
    float lr = s > 0.f ? s : ALPHA * s;
    float w  = expf(-lr);
    int pos = atomicAdd(&g_cursor[src], 1);
    g_csr[pos] = (ull)(unsigned)dst | ((ull)__float_as_uint(w) << 32);
}

// ---------------- gather per node (warp), fused divide+ELU ----------------
__global__ __launch_bounds__(256) void k_gather(float* __restrict__ out) {
    int warp = (blockIdx.x * blockDim.x + threadIdx.x) >> 5;
    int lane = threadIdx.x & 31;
    if (warp >= N_NODES) return;

    int s = g_rowstart[warp];
    int e = g_rowstart[warp + 1];

    float ax = 0.f, ay = 0.f, rs = 0.f;
    int i = s;

    #pragma unroll 1
    for (; i + 8 <= e; i += 8) {
        ull v[8];
        #pragma unroll
        for (int j = 0; j < 8; j++) v[j] = g_csr[i + j];
        float2 hh[8];
        #pragma unroll
        for (int j = 0; j < 8; j++) {
            int d = (int)(unsigned)v[j];
            hh[j] = ((const float2*)(g_h + (size_t)d * OUT_F))[lane];
        }
        #pragma unroll
        for (int j = 0; j < 8; j++) {
            float w = __uint_as_float((unsigned)(v[j] >> 32));
            rs += w;
            ax = fmaf(w, hh[j].x, ax);
            ay = fmaf(w, hh[j].y, ay);
        }
    }
    for (; i < e; i++) {
        ull v = g_csr[i];
        int   d = (int)(unsigned)v;
        float w = __uint_as_float((unsigned)(v >> 32));
        float2 h = ((const float2*)(g_h + (size_t)d * OUT_F))[lane];
        rs += w;
        ax = fmaf(w, h.x, ax);
        ay = fmaf(w, h.y, ay);
    }

    float inv = 1.f / rs;
    float vx = ax * inv;
    float vy = ay * inv;
    vx = vx > 0.f ? vx : expm1f(vx);
    vy = vy > 0.f ? vy : expm1f(vy);
    ((float2*)(out + (size_t)warp * OUT_F))[lane] = make_float2(vx, vy);
}

// ---------------- launch ----------------
extern "C" void kernel_launch(void* const* d_in, const int* in_sizes, int n_in,
                              void* d_out, int out_size) {
    const float* x  = (const float*)d_in[0];
    const float* W  = (const float*)d_in[1];
    const float* a  = (const float*)d_in[2];
    const int*   ei = (const int*)d_in[3];
    float* out = (float*)d_out;

    (void)in_sizes; (void)n_in; (void)out_size;

    // Order chosen so k_gemm is the 4th launch (ncu captures the 4th kernel).
    k_init<<<(N_NODES + 255) / 256, 256>>>();
    k_hist<<<(N_EDGES / 4 + 255) / 256, 256>>>(ei);
    k_scan_a<<<SCAN_BLOCKS, 256>>>();
    k_gemm<<<(N_NODES + 31) / 32, 256>>>(x, W);
    k_scan_b<<<1, 256>>>();
    k_scan_c<<<SCAN_BLOCKS, 256>>>();
    k_scores<<<(N_NODES * 32 + 127) / 128, 128>>>(a);
    k_csr<<<(N_EDGES + 255) / 256, 256>>>(ei);
    k_gather<<<(N_NODES * 32 + 255) / 256, 256>>>(out);
}

// round 6
// speedup vs baseline: 1.6193x; 1.1278x over previous
#include <cuda_runtime.h>
#include <math.h>

#define N_NODES 50000
#define IN_F    256
#define OUT_F   64
#define N_EDGES 1600000
#define ALPHA   0.2f

#define SCAN_BLOCKS 196   // 196*256 = 50176 >= 50000

// gemm tiling
#define GB_NODES 128      // nodes per block
#define GB_THREADS 128
#define KCHUNK 64
#define XS_ROW 65         // padded row (floats) -> conflict-free LDS

typedef unsigned long long ull;

// ---------------- scratch (static device globals; no allocation) ----------------
__device__ __align__(16) float g_h[(size_t)N_NODES * OUT_F];   // 12.8 MB
__device__ float g_s1[N_NODES];
__device__ float g_s2[N_NODES];
__device__ int   g_count[N_NODES];
__device__ int   g_cursor[N_NODES];
__device__ int   g_rowstart[N_NODES + 1];
__device__ int   g_blocksum[SCAN_BLOCKS];
__device__ int   g_blockoff[SCAN_BLOCKS];
__device__ __align__(16) ull g_csr[N_EDGES];                   // 12.8 MB packed (dst, w)

// ---------------- zero histogram ----------------
__global__ void k_init() {
    int idx = blockIdx.x * blockDim.x + threadIdx.x;
    if (idx < N_NODES) g_count[idx] = 0;
}

// ---------------- histogram of src (int4 loads, 4 edges/thread) ----------------
__global__ __launch_bounds__(256) void k_hist(const int* __restrict__ ei) {
    int t = blockIdx.x * blockDim.x + threadIdx.x;
    if (t >= N_EDGES / 4) return;
    int4 v = ((const int4*)ei)[t];
    atomicAdd(&g_count[v.x], 1);
    atomicAdd(&g_count[v.y], 1);
    atomicAdd(&g_count[v.z], 1);
    atomicAdd(&g_count[v.w], 1);
}

// ---------------- scan stage A: per-block sums ----------------
__global__ __launch_bounds__(256) void k_scan_a() {
    __shared__ int sh[256];
    int i = blockIdx.x * 256 + threadIdx.x;
    sh[threadIdx.x] = (i < N_NODES) ? g_count[i] : 0;
    __syncthreads();
    for (int o = 128; o > 0; o >>= 1) {
        if (threadIdx.x < o) sh[threadIdx.x] += sh[threadIdx.x + o];
        __syncthreads();
    }
    if (threadIdx.x == 0) g_blocksum[blockIdx.x] = sh[0];
}

// ---------------- scan stage B: scan of 196 block sums ----------------
__global__ __launch_bounds__(256) void k_scan_b() {
    __shared__ int sh[256];
    int t = threadIdx.x;
    sh[t] = (t < SCAN_BLOCKS) ? g_blocksum[t] : 0;
    __syncthreads();
    #pragma unroll
    for (int o = 1; o < 256; o <<= 1) {
        int v = 0;
        if (t >= o) v = sh[t - o];
        __syncthreads();
        sh[t] += v;
        __syncthreads();
    }
    if (t < SCAN_BLOCKS) g_blockoff[t] = (t == 0) ? 0 : sh[t - 1];
    if (t == 0) g_rowstart[N_NODES] = N_EDGES;
}

// ---------------- scan stage C: block-local exclusive scan + offset ----------------
__global__ __launch_bounds__(256) void k_scan_c() {
    __shared__ int sh[256];
    int t = threadIdx.x;
    int i = blockIdx.x * 256 + t;
    int cnt = (i < N_NODES) ? g_count[i] : 0;
    sh[t] = cnt;
    __syncthreads();
    #pragma unroll
    for (int o = 1; o < 256; o <<= 1) {
        int v = 0;
        if (t >= o) v = sh[t - o];
        __syncthreads();
        sh[t] += v;
        __syncthreads();
    }
    if (i < N_NODES) {
        int excl = g_blockoff[blockIdx.x] + sh[t] - cnt;
        g_rowstart[i] = excl;
        g_cursor[i]   = excl;
    }
}

// ---------------- h = x @ W : register-tiled, packed f32x2 FMA ----------------
// block: 128 nodes x 64 features, 128 threads.
// thread: tx = tid&7 -> features f0=tx*8 (4 f32x2 pairs); ty = tid>>3 -> nodes n0=ty*8.
__global__ __launch_bounds__(GB_THREADS, 4) void k_gemm(const float* __restrict__ x,
                                                        const float* __restrict__ W) {
    __shared__ float xs[GB_NODES * XS_ROW];          // 33.3 KB
    __shared__ __align__(16) ull Wt[32 * (OUT_F/2)]; // 32 k x 64 f as ull pairs, 8 KB

    const int tid = threadIdx.x;
    const int tx = tid & 7;
    const int ty = tid >> 3;
    const int f0 = tx * 8;
    const int n0 = ty * 8;
    const int nodeBase = blockIdx.x * GB_NODES;

    ull acc[8][4];
    #pragma unroll
    for (int j = 0; j < 8; j++)
        #pragma unroll
        for (int p = 0; p < 4; p++) acc[j][p] = 0ull;

    for (int kc = 0; kc < IN_F; kc += KCHUNK) {
        __syncthreads();
        // stage x chunk: 128 nodes x 64 k  (16 float4 per thread, coalesced)
        #pragma unroll
        for (int i = 0; i < (GB_NODES * KCHUNK / 4) / GB_THREADS; i++) {
            int flat = i * GB_THREADS + tid;      // [0, 2048)
            int node = flat >> 4;                 // 16 float4 per node row
            int kv   = flat & 15;
            int gn   = nodeBase + node;
            float4 v = make_float4(0.f, 0.f, 0.f, 0.f);
            if (gn < N_NODES)
                v = *(const float4*)(x + (size_t)gn * IN_F + kc + kv * 4);
            float* dst = &xs[node * XS_ROW + kv * 4];
            dst[0] = v.x; dst[1] = v.y; dst[2] = v.z; dst[3] = v.w;
        }

        #pragma unroll
        for (int h = 0; h < 2; h++) {
            // stage W half-chunk: 32 k x 64 f (4 float4 per thread, coalesced)
            __syncthreads();
            #pragma unroll
            for (int i = 0; i < (32 * OUT_F / 4) / GB_THREADS; i++) {
                int flat = i * GB_THREADS + tid;  // [0, 512)
                int kr = flat >> 4;
                int kv = flat & 15;
                float4 v = *(const float4*)(W + (size_t)(kc + h * 32 + kr) * OUT_F + kv * 4);
                *(float4*)&Wt[kr * (OUT_F/2) + kv * 2] = *(float4*)&v;
            }
            __syncthreads();

            #pragma unroll 4
            for (int k = 0; k < 32; k++) {
                const ull* wrow = &Wt[k * (OUT_F/2) + tx * 4];
                ull w0 = wrow[0], w1 = wrow[1], w2 = wrow[2], w3 = wrow[3];
                // FIX: x column must be offset by the W half-chunk (h*32)
                const float* xcol = &xs[n0 * XS_ROW + h * 32 + k];
                #pragma unroll
                for (int j = 0; j < 8; j++) {
                    float xv = xcol[j * XS_ROW];
                    ull xp;
                    asm("mov.b64 %0, {%1, %1};" : "=l"(xp) : "r"(__float_as_uint(xv)));
                    asm("fma.rn.f32x2 %0, %1, %2, %0;" : "+l"(acc[j][0]) : "l"(xp), "l"(w0));
                    asm("fma.rn.f32x2 %0, %1, %2, %0;" : "+l"(acc[j][1]) : "l"(xp), "l"(w1));
                    asm("fma.rn.f32x2 %0, %1, %2, %0;" : "+l"(acc[j][2]) : "l"(xp), "l"(w2));
                    asm("fma.rn.f32x2 %0, %1, %2, %0;" : "+l"(acc[j][3]) : "l"(xp), "l"(w3));
                }
            }
        }
    }

    // write out: 8 nodes x 8 features per thread (two 16B stores per node)
    #pragma unroll
    for (int j = 0; j < 8; j++) {
        int gn = nodeBase + n0 + j;
        if (gn < N_NODES) {
            ull* dst = (ull*)(g_h + (size_t)gn * OUT_F + f0);
            *(ulonglong2*)(dst)     = make_ulonglong2(acc[j][0], acc[j][1]);
            *(ulonglong2*)(dst + 2) = make_ulonglong2(acc[j][2], acc[j][3]);
        }
    }
}

// ---------------- s1 = h@a1, s2 = h@a2 (one warp per node) ----------------
__global__ __launch_bounds__(128) void k_scores(const float* __restrict__ a) {
    int warp = (blockIdx.x * blockDim.x + threadIdx.x) >> 5;
    int lane = threadIdx.x & 31;
    if (warp >= N_NODES) return;
    float h0 = g_h[(size_t)warp * OUT_F + lane];
    float h1 = g_h[(size_t)warp * OUT_F + 32 + lane];
    float p1 = h0 * a[lane]      + h1 * a[lane + 32];
    float p2 = h0 * a[64 + lane] + h1 * a[96 + lane];
    #pragma unroll
    for (int o = 16; o; o >>= 1) {
        p1 += __shfl_xor_sync(0xFFFFFFFFu, p1, o);
        p2 += __shfl_xor_sync(0xFFFFFFFFu, p2, o);
    }
    if (lane == 0) { g_s1[warp] = p1; g_s2[warp] = p2; }
}

// ---------------- build CSR with packed (dst, w) ----------------
__global__ __launch_bounds__(256) void k_csr(const int* __restrict__ ei) {
    int e = blockIdx.x * blockDim.x + threadIdx.x;
    if (e >= N_EDGES) return;
    int src = ei[e];
    int dst = ei[N_EDGES + e];
    float s  = g_s1[src] + g_s2[dst];
    float lr = s > 0.f ? s : ALPHA * s;
    float w  = expf(-lr);
    int pos = atomicAdd(&g_cursor[src], 1);
    g_csr[pos] = (ull)(unsigned)dst | ((ull)__float_as_uint(w) << 32);
}

// ---------------- gather per node (warp), fused divide+ELU ----------------
__global__ __launch_bounds__(256) void k_gather(float* __restrict__ out) {
    int warp = (blockIdx.x * blockDim.x + threadIdx.x) >> 5;
    int lane = threadIdx.x & 31;
    if (warp >= N_NODES) return;

    int s = g_rowstart[warp];
    int e = g_rowstart[warp + 1];

    float ax = 0.f, ay = 0.f, rs = 0.f;
    int i = s;

    #pragma unroll 1
    for (; i + 8 <= e; i += 8) {
        ull v[8];
        #pragma unroll
        for (int j = 0; j < 8; j++) v[j] = g_csr[i + j];
        float2 hh[8];
        #pragma unroll
        for (int j = 0; j < 8; j++) {
            int d = (int)(unsigned)v[j];
            hh[j] = ((const float2*)(g_h + (size_t)d * OUT_F))[lane];
        }
        #pragma unroll
        for (int j = 0; j < 8; j++) {
            float w = __uint_as_float((unsigned)(v[j] >> 32));
            rs += w;
            ax = fmaf(w, hh[j].x, ax);
            ay = fmaf(w, hh[j].y, ay);
        }
    }
    for (; i < e; i++) {
        ull v = g_csr[i];
        int   d = (int)(unsigned)v;
        float w = __uint_as_float((unsigned)(v >> 32));
        float2 h = ((const float2*)(g_h + (size_t)d * OUT_F))[lane];
        rs += w;
        ax = fmaf(w, h.x, ax);
        ay = fmaf(w, h.y, ay);
    }

    float inv = 1.f / rs;
    float vx = ax * inv;
    float vy = ay * inv;
    vx = vx > 0.f ? vx : expm1f(vx);
    vy = vy > 0.f ? vy : expm1f(vy);
    ((float2*)(out + (size_t)warp * OUT_F))[lane] = make_float2(vx, vy);
}

// ---------------- launch ----------------
extern "C" void kernel_launch(void* const* d_in, const int* in_sizes, int n_in,
                              void* d_out, int out_size) {
    const float* x  = (const float*)d_in[0];
    const float* W  = (const float*)d_in[1];
    const float* a  = (const float*)d_in[2];
    const int*   ei = (const int*)d_in[3];
    float* out = (float*)d_out;

    (void)in_sizes; (void)n_in; (void)out_size;

    // Order chosen so k_gemm is the 4th launch (ncu captures the 4th kernel).
    k_init<<<(N_NODES + 255) / 256, 256>>>();
    k_hist<<<(N_EDGES / 4 + 255) / 256, 256>>>(ei);
    k_scan_a<<<SCAN_BLOCKS, 256>>>();
    k_gemm<<<(N_NODES + GB_NODES - 1) / GB_NODES, GB_THREADS>>>(x, W);
    k_scan_b<<<1, 256>>>();
    k_scan_c<<<SCAN_BLOCKS, 256>>>();
    k_scores<<<(N_NODES * 32 + 127) / 128, 128>>>(a);
    k_csr<<<(N_EDGES + 255) / 256, 256>>>(ei);
    k_gather<<<(N_NODES * 32 + 255) / 256, 256>>>(out);
}

// round 7
// speedup vs baseline: 1.7446x; 1.0773x over previous
#include <cuda_runtime.h>
#include <math.h>

#define N_NODES 50000
#define IN_F    256
#define OUT_F   64
#define N_EDGES 1600000
#define ALPHA   0.2f

#define SCAN_BLOCKS 196   // 196*256 = 50176 >= 50000

// gemm tiling: 128 nodes x 64 f per block, 256 threads, 4n x 8f per thread
#define GB_NODES 128
#define GB_THREADS 256
#define KCHUNK 64
#define XS_ROW 65         // padded x row (floats)
#define WT_ROW 48         // padded W row (ull): 8 groups of 6 ull (4 used + 2 pad)

typedef unsigned long long ull;

// ---------------- scratch (static device globals; no allocation) ----------------
__device__ __align__(16) float g_h[(size_t)N_NODES * OUT_F];   // 12.8 MB
__device__ float g_s1[N_NODES];
__device__ float g_s2[N_NODES];
__device__ int   g_count[N_NODES];
__device__ int   g_cursor[N_NODES];
__device__ int   g_rowstart[N_NODES + 1];
__device__ int   g_blocksum[SCAN_BLOCKS];
__device__ int   g_blockoff[SCAN_BLOCKS];
__device__ __align__(16) ull g_csr[N_EDGES];                   // 12.8 MB packed (dst, w)

// ---------------- zero histogram ----------------
__global__ void k_init() {
    int idx = blockIdx.x * blockDim.x + threadIdx.x;
    if (idx < N_NODES) g_count[idx] = 0;
}

// ---------------- histogram of src (int4 loads, 4 edges/thread) ----------------
__global__ __launch_bounds__(256) void k_hist(const int* __restrict__ ei) {
    int t = blockIdx.x * blockDim.x + threadIdx.x;
    if (t >= N_EDGES / 4) return;
    int4 v = ((const int4*)ei)[t];
    atomicAdd(&g_count[v.x], 1);
    atomicAdd(&g_count[v.y], 1);
    atomicAdd(&g_count[v.z], 1);
    atomicAdd(&g_count[v.w], 1);
}

// ---------------- scan stage A: per-block sums ----------------
__global__ __launch_bounds__(256) void k_scan_a() {
    __shared__ int sh[256];
    int i = blockIdx.x * 256 + threadIdx.x;
    sh[threadIdx.x] = (i < N_NODES) ? g_count[i] : 0;
    __syncthreads();
    for (int o = 128; o > 0; o >>= 1) {
        if (threadIdx.x < o) sh[threadIdx.x] += sh[threadIdx.x + o];
        __syncthreads();
    }
    if (threadIdx.x == 0) g_blocksum[blockIdx.x] = sh[0];
}

// ---------------- scan stage B: scan of 196 block sums ----------------
__global__ __launch_bounds__(256) void k_scan_b() {
    __shared__ int sh[256];
    int t = threadIdx.x;
    sh[t] = (t < SCAN_BLOCKS) ? g_blocksum[t] : 0;
    __syncthreads();
    #pragma unroll
    for (int o = 1; o < 256; o <<= 1) {
        int v = 0;
        if (t >= o) v = sh[t - o];
        __syncthreads();
        sh[t] += v;
        __syncthreads();
    }
    if (t < SCAN_BLOCKS) g_blockoff[t] = (t == 0) ? 0 : sh[t - 1];
    if (t == 0) g_rowstart[N_NODES] = N_EDGES;
}

// ---------------- scan stage C: block-local exclusive scan + offset ----------------
__global__ __launch_bounds__(256) void k_scan_c() {
    __shared__ int sh[256];
    int t = threadIdx.x;
    int i = blockIdx.x * 256 + t;
    int cnt = (i < N_NODES) ? g_count[i] : 0;
    sh[t] = cnt;
    __syncthreads();
    #pragma unroll
    for (int o = 1; o < 256; o <<= 1) {
        int v = 0;
        if (t >= o) v = sh[t - o];
        __syncthreads();
        sh[t] += v;
        __syncthreads();
    }
    if (i < N_NODES) {
        int excl = g_blockoff[blockIdx.x] + sh[t] - cnt;
        g_rowstart[i] = excl;
        g_cursor[i]   = excl;
    }
}

// ---------------- h = x @ W with fused attention scores ----------------
// 256 threads: tx = tid&7 -> features f0 = tx*8; ty = tid>>3 -> nodes n0 = ty*4.
// Each thread: 4 nodes x 8 features = 16 f32x2 accumulators.
// Epilogue: store h AND compute s1/s2 via shfl reduction over the 8 tx lanes.
__global__ __launch_bounds__(GB_THREADS, 3) void k_gemm(const float* __restrict__ x,
                                                        const float* __restrict__ W,
                                                        const float* __restrict__ a) {
    __shared__ float xs[GB_NODES * XS_ROW];            // 33.3 KB
    __shared__ __align__(16) ull Wt[KCHUNK * WT_ROW];  // 24 KB

    const int tid = threadIdx.x;
    const int tx = tid & 7;
    const int ty = tid >> 3;
    const int f0 = tx * 8;
    const int n0 = ty * 4;
    const int nodeBase = blockIdx.x * GB_NODES;

    ull acc[4][4];
    #pragma unroll
    for (int j = 0; j < 4; j++)
        #pragma unroll
        for (int p = 0; p < 4; p++) acc[j][p] = 0ull;

    for (int kc = 0; kc < IN_F; kc += KCHUNK) {
        __syncthreads();
        // stage x chunk: 128 nodes x 64 k (8 float4 per thread, coalesced)
        #pragma unroll
        for (int i = 0; i < (GB_NODES * KCHUNK / 4) / GB_THREADS; i++) {
            int flat = i * GB_THREADS + tid;      // [0, 2048)
            int node = flat >> 4;
            int kv   = flat & 15;
            int gn   = nodeBase + node;
            float4 v = make_float4(0.f, 0.f, 0.f, 0.f);
            if (gn < N_NODES)
                v = *(const float4*)(x + (size_t)gn * IN_F + kc + kv * 4);
            float* dst = &xs[node * XS_ROW + kv * 4];
            dst[0] = v.x; dst[1] = v.y; dst[2] = v.z; dst[3] = v.w;
        }
        // stage W chunk: 64 k x 64 f (4 float4 per thread, coalesced, padded groups)
        #pragma unroll
        for (int i = 0; i < (KCHUNK * OUT_F / 4) / GB_THREADS; i++) {
            int flat = i * GB_THREADS + tid;      // [0, 1024)
            int kr = flat >> 4;
            int kv = flat & 15;                   // float4 index along f
            float4 v = *(const float4*)(W + (size_t)(kc + kr) * OUT_F + kv * 4);
            // group = kv>>1 (8 features per group), offset within group = (kv&1)*2 ull
            *(ulonglong2*)&Wt[kr * WT_ROW + (kv >> 1) * 6 + (kv & 1) * 2] =
                *(ulonglong2*)&v;
        }
        __syncthreads();

        #pragma unroll 4
        for (int k = 0; k < KCHUNK; k++) {
            const ull* wrow = &Wt[k * WT_ROW + tx * 6];
            ull w0 = wrow[0], w1 = wrow[1], w2 = wrow[2], w3 = wrow[3];
            const float* xcol = &xs[n0 * XS_ROW + k];
            #pragma unroll
            for (int j = 0; j < 4; j++) {
                float xv = xcol[j * XS_ROW];
                ull xp;
                asm("mov.b64 %0, {%1, %1};" : "=l"(xp) : "r"(__float_as_uint(xv)));
                asm("fma.rn.f32x2 %0, %1, %2, %0;" : "+l"(acc[j][0]) : "l"(xp), "l"(w0));
                asm("fma.rn.f32x2 %0, %1, %2, %0;" : "+l"(acc[j][1]) : "l"(xp), "l"(w1));
                asm("fma.rn.f32x2 %0, %1, %2, %0;" : "+l"(acc[j][2]) : "l"(xp), "l"(w2));
                asm("fma.rn.f32x2 %0, %1, %2, %0;" : "+l"(acc[j][3]) : "l"(xp), "l"(w3));
            }
        }
    }

    // epilogue: write h, compute fused scores s1 = h@a1, s2 = h@a2
    float a1[8], a2[8];
    #pragma unroll
    for (int i = 0; i < 8; i++) {
        a1[i] = __ldg(a + f0 + i);
        a2[i] = __ldg(a + OUT_F + f0 + i);
    }

    #pragma unroll
    for (int j = 0; j < 4; j++) {
        int gn = nodeBase + n0 + j;
        float hf[8];
        #pragma unroll
        for (int p = 0; p < 4; p++) {
            hf[2 * p]     = __uint_as_float((unsigned)acc[j][p]);
            hf[2 * p + 1] = __uint_as_float((unsigned)(acc[j][p] >> 32));
        }
        if (gn < N_NODES) {
            ull* dst = (ull*)(g_h + (size_t)gn * OUT_F + f0);
            *(ulonglong2*)(dst)     = make_ulonglong2(acc[j][0], acc[j][1]);
            *(ulonglong2*)(dst + 2) = make_ulonglong2(acc[j][2], acc[j][3]);
        }
        float s1 = 0.f, s2 = 0.f;
        #pragma unroll
        for (int i = 0; i < 8; i++) {
            s1 = fmaf(hf[i], a1[i], s1);
            s2 = fmaf(hf[i], a2[i], s2);
        }
        #pragma unroll
        for (int o = 1; o < 8; o <<= 1) {
            s1 += __shfl_xor_sync(0xFFFFFFFFu, s1, o);
            s2 += __shfl_xor_sync(0xFFFFFFFFu, s2, o);
        }
        if (tx == 0 && gn < N_NODES) {
            g_s1[gn] = s1;
            g_s2[gn] = s2;
        }
    }
}

// ---------------- build CSR with packed (dst, w) ----------------
__global__ __launch_bounds__(256) void k_csr(const int* __restrict__ ei) {
    int e = blockIdx.x * blockDim.x + threadIdx.x;
    if (e >= N_EDGES) return;
    int src = ei[e];
    int dst = ei[N_EDGES + e];
    float s  = g_s1[src] + g_s2[dst];
    float lr = s > 0.f ? s : ALPHA * s;
    float w  = expf(-lr);
    int pos = atomicAdd(&g_cursor[src], 1);
    g_csr[pos] = (ull)(unsigned)dst | ((ull)__float_as_uint(w) << 32);
}

// ---------------- gather per node (warp), fused divide+ELU ----------------
__global__ __launch_bounds__(256) void k_gather(float* __restrict__ out) {
    int warp = (blockIdx.x * blockDim.x + threadIdx.x) >> 5;
    int lane = threadIdx.x & 31;
    if (warp >= N_NODES) return;

    int s = g_rowstart[warp];
    int e = g_rowstart[warp + 1];

    float ax = 0.f, ay = 0.f, rs = 0.f;
    int i = s;

    #pragma unroll 1
    for (; i + 8 <= e; i += 8) {
        ull v[8];
        #pragma unroll
        for (int j = 0; j < 8; j++) v[j] = g_csr[i + j];
        float2 hh[8];
        #pragma unroll
        for (int j = 0; j < 8; j++) {
            int d = (int)(unsigned)v[j];
            hh[j] = ((const float2*)(g_h + (size_t)d * OUT_F))[lane];
        }
        #pragma unroll
        for (int j = 0; j < 8; j++) {
            float w = __uint_as_float((unsigned)(v[j] >> 32));
            rs += w;
            ax = fmaf(w, hh[j].x, ax);
            ay = fmaf(w, hh[j].y, ay);
        }
    }
    for (; i < e; i++) {
        ull v = g_csr[i];
        int   d = (int)(unsigned)v;
        float w = __uint_as_float((unsigned)(v >> 32));
        float2 h = ((const float2*)(g_h + (size_t)d * OUT_F))[lane];
        rs += w;
        ax = fmaf(w, h.x, ax);
        ay = fmaf(w, h.y, ay);
    }

    float inv = 1.f / rs;
    float vx = ax * inv;
    float vy = ay * inv;
    vx = vx > 0.f ? vx : expm1f(vx);
    vy = vy > 0.f ? vy : expm1f(vy);
    ((float2*)(out + (size_t)warp * OUT_F))[lane] = make_float2(vx, vy);
}

// ---------------- launch ----------------
extern "C" void kernel_launch(void* const* d_in, const int* in_sizes, int n_in,
                              void* d_out, int out_size) {
    const float* x  = (const float*)d_in[0];
    const float* W  = (const float*)d_in[1];
    const float* a  = (const float*)d_in[2];
    const int*   ei = (const int*)d_in[3];
    float* out = (float*)d_out;

    (void)in_sizes; (void)n_in; (void)out_size;

    // Order chosen so k_gemm is the 4th launch (ncu captures the 4th kernel).
    k_init<<<(N_NODES + 255) / 256, 256>>>();
    k_hist<<<(N_EDGES / 4 + 255) / 256, 256>>>(ei);
    k_scan_a<<<SCAN_BLOCKS, 256>>>();
    k_gemm<<<(N_NODES + GB_NODES - 1) / GB_NODES, GB_THREADS>>>(x, W, a);
    k_scan_b<<<1, 256>>>();
    k_scan_c<<<SCAN_BLOCKS, 256>>>();
    k_csr<<<(N_EDGES + 255) / 256, 256>>>(ei);
    k_gather<<<(N_NODES * 32 + 255) / 256, 256>>>(out);
}

// round 8
// speedup vs baseline: 1.7595x; 1.0086x over previous
#include <cuda_runtime.h>
#include <math.h>

#define N_NODES 50000
#define IN_F    256
#define OUT_F   64
#define N_EDGES 1600000
#define ALPHA   0.2f

#define SCAN_BLOCKS 196   // 196*256 = 50176 >= 50000

// gemm tiling: 128 nodes x 64 f per block, 256 threads, 4n x 8f per thread
#define GB_NODES 128
#define GB_THREADS 256
#define KC2 128             // k-chunk for W staging
#define SLAB 514            // ull per W slab: 128k*4 ull + 2 pad (bank-offset trick)

typedef unsigned long long ull;

// ---------------- scratch (static device globals; no allocation) ----------------
__device__ __align__(16) float g_h[(size_t)N_NODES * OUT_F];   // 12.8 MB
__device__ float g_s1[N_NODES];
__device__ float g_s2[N_NODES];
__device__ int   g_count[N_NODES];
__device__ int   g_cursor[N_NODES];
__device__ int   g_rowstart[N_NODES + 1];
__device__ int   g_blocksum[SCAN_BLOCKS];
__device__ int   g_blockoff[SCAN_BLOCKS];
__device__ __align__(16) ull g_csr[N_EDGES];                   // 12.8 MB packed (dst, w)

// ---------------- zero histogram ----------------
__global__ void k_init() {
    int idx = blockIdx.x * blockDim.x + threadIdx.x;
    if (idx < N_NODES) g_count[idx] = 0;
}

// ---------------- histogram of src (int4 loads, 4 edges/thread) ----------------
__global__ __launch_bounds__(256) void k_hist(const int* __restrict__ ei) {
    int t = blockIdx.x * blockDim.x + threadIdx.x;
    if (t >= N_EDGES / 4) return;
    int4 v = ((const int4*)ei)[t];
    atomicAdd(&g_count[v.x], 1);
    atomicAdd(&g_count[v.y], 1);
    atomicAdd(&g_count[v.z], 1);
    atomicAdd(&g_count[v.w], 1);
}

// ---------------- scan stage A: per-block sums ----------------
__global__ __launch_bounds__(256) void k_scan_a() {
    __shared__ int sh[256];
    int i = blockIdx.x * 256 + threadIdx.x;
    sh[threadIdx.x] = (i < N_NODES) ? g_count[i] : 0;
    __syncthreads();
    for (int o = 128; o > 0; o >>= 1) {
        if (threadIdx.x < o) sh[threadIdx.x] += sh[threadIdx.x + o];
        __syncthreads();
    }
    if (threadIdx.x == 0) g_blocksum[blockIdx.x] = sh[0];
}

// ---------------- scan stage B: scan of 196 block sums ----------------
__global__ __launch_bounds__(256) void k_scan_b() {
    __shared__ int sh[256];
    int t = threadIdx.x;
    sh[t] = (t < SCAN_BLOCKS) ? g_blocksum[t] : 0;
    __syncthreads();
    #pragma unroll
    for (int o = 1; o < 256; o <<= 1) {
        int v = 0;
        if (t >= o) v = sh[t - o];
        __syncthreads();
        sh[t] += v;
        __syncthreads();
    }
    if (t < SCAN_BLOCKS) g_blockoff[t] = (t == 0) ? 0 : sh[t - 1];
    if (t == 0) g_rowstart[N_NODES] = N_EDGES;
}

// ---------------- scan stage C: block-local exclusive scan + offset ----------------
__global__ __launch_bounds__(256) void k_scan_c() {
    __shared__ int sh[256];
    int t = threadIdx.x;
    int i = blockIdx.x * 256 + t;
    int cnt = (i < N_NODES) ? g_count[i] : 0;
    sh[t] = cnt;
    __syncthreads();
    #pragma unroll
    for (int o = 1; o < 256; o <<= 1) {
        int v = 0;
        if (t >= o) v = sh[t - o];
        __syncthreads();
        sh[t] += v;
        __syncthreads();
    }
    if (i < N_NODES) {
        int excl = g_blockoff[blockIdx.x] + sh[t] - cnt;
        g_rowstart[i] = excl;
        g_cursor[i]   = excl;
    }
}

// ---------------- h = x @ W with fused attention scores ----------------
// 256 threads: tx = tid&7 -> features f0 = tx*8; ty = tid>>3 -> nodes n0 = ty*4.
// x is read straight from global (per-octet broadcast LDG.128, minimal traffic);
// W staged in smem slabs (one slab per tx group, padded for conflict-free LDS.128).
__global__ __launch_bounds__(GB_THREADS, 3) void k_gemm(const float* __restrict__ x,
                                                        const float* __restrict__ W,
                                                        const float* __restrict__ a) {
    __shared__ __align__(16) ull Wt[8 * SLAB];   // 32.9 KB

    const int tid = threadIdx.x;
    const int tx = tid & 7;
    const int ty = tid >> 3;
    const int f0 = tx * 8;
    const int nodeBase = blockIdx.x * GB_NODES + ty * 4;

    // clamped x row pointers (tail block reads row 0 area harmlessly)
    const float* xr[4];
    #pragma unroll
    for (int j = 0; j < 4; j++) {
        int gn = nodeBase + j;
        if (gn >= N_NODES) gn = N_NODES - 1;
        xr[j] = x + (size_t)gn * IN_F;
    }

    ull acc[4][4];
    #pragma unroll
    for (int j = 0; j < 4; j++)
        #pragma unroll
        for (int p = 0; p < 4; p++) acc[j][p] = 0ull;

    for (int kc = 0; kc < IN_F; kc += KC2) {
        __syncthreads();
        // stage W chunk: 128 k x 64 f -> 2048 float4, 8 per thread (coalesced)
        #pragma unroll
        for (int i = 0; i < (KC2 * OUT_F / 4) / GB_THREADS; i++) {
            int flat = i * GB_THREADS + tid;   // [0, 2048)
            int kr = flat >> 4;
            int kv = flat & 15;
            float4 v = *(const float4*)(W + (size_t)(kc + kr) * OUT_F + kv * 4);
            *(ulonglong2*)&Wt[(kv >> 1) * SLAB + kr * 4 + (kv & 1) * 2] =
                *(ulonglong2*)&v;
        }
        __syncthreads();

        const ull* wslab = &Wt[tx * SLAB];
        #pragma unroll 2
        for (int k4 = 0; k4 < KC2; k4 += 4) {
            float4 xv[4];
            #pragma unroll
            for (int j = 0; j < 4; j++)
                xv[j] = __ldg((const float4*)(xr[j] + kc + k4));
            #pragma unroll
            for (int kk = 0; kk < 4; kk++) {
                const ull* wrow = wslab + (k4 + kk) * 4;
                ull w0 = wrow[0], w1 = wrow[1], w2 = wrow[2], w3 = wrow[3];
                #pragma unroll
                for (int j = 0; j < 4; j++) {
                    float xf = (kk == 0) ? xv[j].x : (kk == 1) ? xv[j].y
                             : (kk == 2) ? xv[j].z : xv[j].w;
                    ull xp;
                    asm("mov.b64 %0, {%1, %1};" : "=l"(xp) : "r"(__float_as_uint(xf)));
                    asm("fma.rn.f32x2 %0, %1, %2, %0;" : "+l"(acc[j][0]) : "l"(xp), "l"(w0));
                    asm("fma.rn.f32x2 %0, %1, %2, %0;" : "+l"(acc[j][1]) : "l"(xp), "l"(w1));
                    asm("fma.rn.f32x2 %0, %1, %2, %0;" : "+l"(acc[j][2]) : "l"(xp), "l"(w2));
                    asm("fma.rn.f32x2 %0, %1, %2, %0;" : "+l"(acc[j][3]) : "l"(xp), "l"(w3));
                }
            }
        }
    }

    // epilogue: write h, compute fused scores s1 = h@a1, s2 = h@a2
    float a1[8], a2[8];
    #pragma unroll
    for (int i = 0; i < 8; i++) {
        a1[i] = __ldg(a + f0 + i);
        a2[i] = __ldg(a + OUT_F + f0 + i);
    }

    #pragma unroll
    for (int j = 0; j < 4; j++) {
        int gn = nodeBase + j;
        float hf[8];
        #pragma unroll
        for (int p = 0; p < 4; p++) {
            hf[2 * p]     = __uint_as_float((unsigned)acc[j][p]);
            hf[2 * p + 1] = __uint_as_float((unsigned)(acc[j][p] >> 32));
        }
        if (gn < N_NODES) {
            ull* dst = (ull*)(g_h + (size_t)gn * OUT_F + f0);
            *(ulonglong2*)(dst)     = make_ulonglong2(acc[j][0], acc[j][1]);
            *(ulonglong2*)(dst + 2) = make_ulonglong2(acc[j][2], acc[j][3]);
        }
        float s1 = 0.f, s2 = 0.f;
        #pragma unroll
        for (int i = 0; i < 8; i++) {
            s1 = fmaf(hf[i], a1[i], s1);
            s2 = fmaf(hf[i], a2[i], s2);
        }
        #pragma unroll
        for (int o = 1; o < 8; o <<= 1) {
            s1 += __shfl_xor_sync(0xFFFFFFFFu, s1, o);
            s2 += __shfl_xor_sync(0xFFFFFFFFu, s2, o);
        }
        if (tx == 0 && gn < N_NODES) {
            g_s1[gn] = s1;
            g_s2[gn] = s2;
        }
    }
}

// ---------------- build CSR with packed (dst, w) ----------------
__global__ __launch_bounds__(256) void k_csr(const int* __restrict__ ei) {
    int e = blockIdx.x * blockDim.x + threadIdx.x;
    if (e >= N_EDGES) return;
    int src = ei[e];
    int dst = ei[N_EDGES + e];
    float s  = g_s1[src] + g_s2[dst];
    float lr = s > 0.f ? s : ALPHA * s;
    float w  = expf(-lr);
    int pos = atomicAdd(&g_cursor[src], 1);
    g_csr[pos] = (ull)(unsigned)dst | ((ull)__float_as_uint(w) << 32);
}

// ---------------- gather per node (warp), fused divide+ELU ----------------
__global__ __launch_bounds__(256) void k_gather(float* __restrict__ out) {
    int warp = (blockIdx.x * blockDim.x + threadIdx.x) >> 5;
    int lane = threadIdx.x & 31;
    if (warp >= N_NODES) return;

    int s = g_rowstart[warp];
    int e = g_rowstart[warp + 1];

    float ax = 0.f, ay = 0.f, rs = 0.f;
    int i = s;

    #pragma unroll 1
    for (; i + 8 <= e; i += 8) {
        ull v[8];
        #pragma unroll
        for (int j = 0; j < 8; j++) v[j] = g_csr[i + j];
        float2 hh[8];
        #pragma unroll
        for (int j = 0; j < 8; j++) {
            int d = (int)(unsigned)v[j];
            hh[j] = ((const float2*)(g_h + (size_t)d * OUT_F))[lane];
        }
        #pragma unroll
        for (int j = 0; j < 8; j++) {
            float w = __uint_as_float((unsigned)(v[j] >> 32));
            rs += w;
            ax = fmaf(w, hh[j].x, ax);
            ay = fmaf(w, hh[j].y, ay);
        }
    }
    for (; i < e; i++) {
        ull v = g_csr[i];
        int   d = (int)(unsigned)v;
        float w = __uint_as_float((unsigned)(v >> 32));
        float2 h = ((const float2*)(g_h + (size_t)d * OUT_F))[lane];
        rs += w;
        ax = fmaf(w, h.x, ax);
        ay = fmaf(w, h.y, ay);
    }

    float inv = 1.f / rs;
    float vx = ax * inv;
    float vy = ay * inv;
    vx = vx > 0.f ? vx : expm1f(vx);
    vy = vy > 0.f ? vy : expm1f(vy);
    ((float2*)(out + (size_t)warp * OUT_F))[lane] = make_float2(vx, vy);
}

// ---------------- launch ----------------
extern "C" void kernel_launch(void* const* d_in, const int* in_sizes, int n_in,
                              void* d_out, int out_size) {
    const float* x  = (const float*)d_in[0];
    const float* W  = (const float*)d_in[1];
    const float* a  = (const float*)d_in[2];
    const int*   ei = (const int*)d_in[3];
    float* out = (float*)d_out;

    (void)in_sizes; (void)n_in; (void)out_size;

    // Fork: [init -> hist -> scan_a] on side stream, gemm on main stream.
    // Host-side stream/event creation only (no device memory). Objects are
    // intentionally not destroyed (capture may still reference them); only a
    // handful of calls ever happen, replays re-execute the captured graph.
    cudaStream_t s2;
    cudaEvent_t e1, e2;
    cudaStreamCreateWithFlags(&s2, cudaStreamNonBlocking);
    cudaEventCreateWithFlags(&e1, cudaEventDisableTiming);
    cudaEventCreateWithFlags(&e2, cudaEventDisableTiming);

    cudaEventRecord(e1, 0);
    cudaStreamWaitEvent(s2, e1, 0);

    k_init<<<(N_NODES + 255) / 256, 256, 0, s2>>>();
    k_hist<<<(N_EDGES / 4 + 255) / 256, 256, 0, s2>>>(ei);
    k_scan_a<<<SCAN_BLOCKS, 256, 0, s2>>>();

    k_gemm<<<(N_NODES + GB_NODES - 1) / GB_NODES, GB_THREADS>>>(x, W, a);

    cudaEventRecord(e2, s2);
    cudaStreamWaitEvent(0, e2, 0);

    k_scan_b<<<1, 256>>>();
    k_scan_c<<<SCAN_BLOCKS, 256>>>();
    k_csr<<<(N_EDGES + 255) / 256, 256>>>(ei);
    k_gather<<<(N_NODES * 32 + 255) / 256, 256>>>(out);
}

// round 10
// speedup vs baseline: 1.7616x; 1.0012x over previous
#include <cuda_runtime.h>
#include <math.h>

#define N_NODES 50000
#define IN_F    256
#define OUT_F   64
#define N_EDGES 1600000
#define ALPHA   0.2f

#define SCAN_BLOCKS 196   // 196*256 = 50176 >= 50000

// gemm tiling (R7 config): 128 nodes x 64 f per block, 256 threads, 4n x 8f per thread
#define GB_NODES 128
#define GB_THREADS 256
#define KCHUNK 64
#define XS_ROW 65
#define WT_ROW 48

typedef unsigned long long ull;

// ---------------- scratch (static device globals; no allocation) ----------------
__device__ __align__(16) float g_h[(size_t)N_NODES * OUT_F];   // 12.8 MB
__device__ float g_s1[N_NODES];
__device__ float g_s2[N_NODES];
__device__ int   g_count[N_NODES];
__device__ int   g_rowstart[N_NODES + 1];
__device__ int   g_blocksum[SCAN_BLOCKS];
__device__ int   g_blockoff[SCAN_BLOCKS];
__device__ __align__(16) int g_rank[N_EDGES];                  // 6.4 MB
__device__ float g_u1[IN_F];
__device__ float g_u2[IN_F];
__device__ __align__(16) ull g_csr[N_EDGES];                   // 12.8 MB packed (dst, w)

// ---------------- zero histogram ----------------
__global__ void k_init() {
    int idx = blockIdx.x * blockDim.x + threadIdx.x;
    if (idx < N_NODES) g_count[idx] = 0;
}

// ---------------- histogram of src + per-edge rank ----------------
__global__ __launch_bounds__(256) void k_hist_rank(const int* __restrict__ ei) {
    int t = blockIdx.x * blockDim.x + threadIdx.x;
    if (t >= N_EDGES / 4) return;
    int4 v = ((const int4*)ei)[t];
    int4 r;
    r.x = atomicAdd(&g_count[v.x], 1);
    r.y = atomicAdd(&g_count[v.y], 1);
    r.z = atomicAdd(&g_count[v.z], 1);
    r.w = atomicAdd(&g_count[v.w], 1);
    ((int4*)g_rank)[t] = r;
}

// ---------------- scan stage A: per-block sums ----------------
__global__ __launch_bounds__(256) void k_scan_a() {
    __shared__ int sh[256];
    int i = blockIdx.x * 256 + threadIdx.x;
    sh[threadIdx.x] = (i < N_NODES) ? g_count[i] : 0;
    __syncthreads();
    for (int o = 128; o > 0; o >>= 1) {
        if (threadIdx.x < o) sh[threadIdx.x] += sh[threadIdx.x + o];
        __syncthreads();
    }
    if (threadIdx.x == 0) g_blocksum[blockIdx.x] = sh[0];
}

// ---------------- scan stage B (+ fused u1/u2 = W@a1, W@a2) ----------------
__global__ __launch_bounds__(256) void k_scan_b_u(const float* __restrict__ W,
                                                  const float* __restrict__ a) {
    __shared__ int sh[256];
    int t = threadIdx.x;
    sh[t] = (t < SCAN_BLOCKS) ? g_blocksum[t] : 0;
    __syncthreads();
    #pragma unroll
    for (int o = 1; o < 256; o <<= 1) {
        int v = 0;
        if (t >= o) v = sh[t - o];
        __syncthreads();
        sh[t] += v;
        __syncthreads();
    }
    if (t < SCAN_BLOCKS) g_blockoff[t] = (t == 0) ? 0 : sh[t - 1];
    if (t == 0) g_rowstart[N_NODES] = N_EDGES;

    // u1[k] = sum_f W[k][f] * a[f];  u2[k] = sum_f W[k][f] * a[64+f]
    float u1 = 0.f, u2 = 0.f;
    const float* wrow = W + (size_t)t * OUT_F;
    #pragma unroll 8
    for (int f = 0; f < OUT_F; f++) {
        float wv = wrow[f];
        u1 = fmaf(wv, __ldg(a + f), u1);
        u2 = fmaf(wv, __ldg(a + OUT_F + f), u2);
    }
    g_u1[t] = u1;
    g_u2[t] = u2;
}

// ---------------- scan stage C: block-local exclusive scan -> rowstart ----------------
__global__ __launch_bounds__(256) void k_scan_c() {
    __shared__ int sh[256];
    int t = threadIdx.x;
    int i = blockIdx.x * 256 + t;
    int cnt = (i < N_NODES) ? g_count[i] : 0;
    sh[t] = cnt;
    __syncthreads();
    #pragma unroll
    for (int o = 1; o < 256; o <<= 1) {
        int v = 0;
        if (t >= o) v = sh[t - o];
        __syncthreads();
        sh[t] += v;
        __syncthreads();
    }
    if (i < N_NODES) g_rowstart[i] = g_blockoff[blockIdx.x] + sh[t] - cnt;
}

// ---------------- scores from x: s1 = x@u1, s2 = x@u2 (one warp per node) --------
__global__ __launch_bounds__(256) void k_sx(const float* __restrict__ x) {
    int warp = (blockIdx.x * blockDim.x + threadIdx.x) >> 5;
    int lane = threadIdx.x & 31;
    if (warp >= N_NODES) return;
    const float4* xr = (const float4*)(x + (size_t)warp * IN_F);
    float4 xa = __ldg(xr + lane * 2);
    float4 xb = __ldg(xr + lane * 2 + 1);
    float4 ua = *(const float4*)(g_u1 + lane * 8);
    float4 ub = *(const float4*)(g_u1 + lane * 8 + 4);
    float4 va = *(const float4*)(g_u2 + lane * 8);
    float4 vb = *(const float4*)(g_u2 + lane * 8 + 4);
    float s1 = xa.x * ua.x + xa.y * ua.y + xa.z * ua.z + xa.w * ua.w
             + xb.x * ub.x + xb.y * ub.y + xb.z * ub.z + xb.w * ub.w;
    float s2 = xa.x * va.x + xa.y * va.y + xa.z * va.z + xa.w * va.w
             + xb.x * vb.x + xb.y * vb.y + xb.z * vb.z + xb.w * vb.w;
    #pragma unroll
    for (int o = 16; o; o >>= 1) {
        s1 += __shfl_xor_sync(0xFFFFFFFFu, s1, o);
        s2 += __shfl_xor_sync(0xFFFFFFFFu, s2, o);
    }
    if (lane == 0) { g_s1[warp] = s1; g_s2[warp] = s2; }
}

// ---------------- h = x @ W (R7 tiling, no score epilogue) ----------------
__global__ __launch_bounds__(GB_THREADS, 3) void k_gemm(const float* __restrict__ x,
                                                        const float* __restrict__ W) {
    __shared__ float xs[GB_NODES * XS_ROW];
    __shared__ __align__(16) ull Wt[KCHUNK * WT_ROW];

    const int tid = threadIdx.x;
    const int tx = tid & 7;
    const int ty = tid >> 3;
    const int f0 = tx * 8;
    const int n0 = ty * 4;
    const int nodeBase = blockIdx.x * GB_NODES;

    ull acc[4][4];
    #pragma unroll
    for (int j = 0; j < 4; j++)
        #pragma unroll
        for (int p = 0; p < 4; p++) acc[j][p] = 0ull;

    for (int kc = 0; kc < IN_F; kc += KCHUNK) {
        __syncthreads();
        #pragma unroll
        for (int i = 0; i < (GB_NODES * KCHUNK / 4) / GB_THREADS; i++) {
            int flat = i * GB_THREADS + tid;
            int node = flat >> 4;
            int kv   = flat & 15;
            int gn   = nodeBase + node;
            float4 v = make_float4(0.f, 0.f, 0.f, 0.f);
            if (gn < N_NODES)
                v = *(const float4*)(x + (size_t)gn * IN_F + kc + kv * 4);
            float* dst = &xs[node * XS_ROW + kv * 4];
            dst[0] = v.x; dst[1] = v.y; dst[2] = v.z; dst[3] = v.w;
        }
        #pragma unroll
        for (int i = 0; i < (KCHUNK * OUT_F / 4) / GB_THREADS; i++) {
            int flat = i * GB_THREADS + tid;
            int kr = flat >> 4;
            int kv = flat & 15;
            float4 v = *(const float4*)(W + (size_t)(kc + kr) * OUT_F + kv * 4);
            *(ulonglong2*)&Wt[kr * WT_ROW + (kv >> 1) * 6 + (kv & 1) * 2] =
                *(ulonglong2*)&v;
        }
        __syncthreads();

        #pragma unroll 4
        for (int k = 0; k < KCHUNK; k++) {
            const ull* wrow = &Wt[k * WT_ROW + tx * 6];
            ull w0 = wrow[0], w1 = wrow[1], w2 = wrow[2], w3 = wrow[3];
            const float* xcol = &xs[n0 * XS_ROW + k];
            #pragma unroll
            for (int j = 0; j < 4; j++) {
                float xv = xcol[j * XS_ROW];
                ull xp;
                asm("mov.b64 %0, {%1, %1};" : "=l"(xp) : "r"(__float_as_uint(xv)));
                asm("fma.rn.f32x2 %0, %1, %2, %0;" : "+l"(acc[j][0]) : "l"(xp), "l"(w0));
                asm("fma.rn.f32x2 %0, %1, %2, %0;" : "+l"(acc[j][1]) : "l"(xp), "l"(w1));
                asm("fma.rn.f32x2 %0, %1, %2, %0;" : "+l"(acc[j][2]) : "l"(xp), "l"(w2));
                asm("fma.rn.f32x2 %0, %1, %2, %0;" : "+l"(acc[j][3]) : "l"(xp), "l"(w3));
            }
        }
    }

    #pragma unroll
    for (int j = 0; j < 4; j++) {
        int gn = nodeBase + n0 + j;
        if (gn < N_NODES) {
            ull* dst = (ull*)(g_h + (size_t)gn * OUT_F + f0);
            *(ulonglong2*)(dst)     = make_ulonglong2(acc[j][0], acc[j][1]);
            *(ulonglong2*)(dst + 2) = make_ulonglong2(acc[j][2], acc[j][3]);
        }
    }
}

// ---------------- build CSR (atomic-free, rank precomputed) ----------------
__global__ __launch_bounds__(256) void k_csr(const int* __restrict__ ei) {
    int e = blockIdx.x * blockDim.x + threadIdx.x;
    if (e >= N_EDGES) return;
    int src = ei[e];
    int dst = ei[N_EDGES + e];
    float s  = g_s1[src] + g_s2[dst];
    float lr = s > 0.f ? s : ALPHA * s;
    float w  = expf(-lr);
    int pos = g_rowstart[src] + g_rank[e];
    g_csr[pos] = (ull)(unsigned)dst | ((ull)__float_as_uint(w) << 32);
}

// ---------------- gather per node (warp), fused divide+ELU ----------------
__global__ __launch_bounds__(256) void k_gather(float* __restrict__ out) {
    int warp = (blockIdx.x * blockDim.x + threadIdx.x) >> 5;
    int lane = threadIdx.x & 31;
    if (warp >= N_NODES) return;

    int s = g_rowstart[warp];
    int e = g_rowstart[warp + 1];

    float ax = 0.f, ay = 0.f, rs = 0.f;
    int i = s;

    #pragma unroll 1
    for (; i + 8 <= e; i += 8) {
        ull v[8];
        #pragma unroll
        for (int j = 0; j < 8; j++) v[j] = g_csr[i + j];
        float2 hh[8];
        #pragma unroll
        for (int j = 0; j < 8; j++) {
            int d = (int)(unsigned)v[j];
            hh[j] = ((const float2*)(g_h + (size_t)d * OUT_F))[lane];
        }
        #pragma unroll
        for (int j = 0; j < 8; j++) {
            float w = __uint_as_float((unsigned)(v[j] >> 32));
            rs += w;
            ax = fmaf(w, hh[j].x, ax);
            ay = fmaf(w, hh[j].y, ay);
        }
    }
    for (; i < e; i++) {
        ull v = g_csr[i];
        int   d = (int)(unsigned)v;
        float w = __uint_as_float((unsigned)(v >> 32));
        float2 h = ((const float2*)(g_h + (size_t)d * OUT_F))[lane];
        rs += w;
        ax = fmaf(w, h.x, ax);
        ay = fmaf(w, h.y, ay);
    }

    float inv = 1.f / rs;
    float vx = ax * inv;
    float vy = ay * inv;
    vx = vx > 0.f ? vx : expm1f(vx);
    vy = vy > 0.f ? vy : expm1f(vy);
    ((float2*)(out + (size_t)warp * OUT_F))[lane] = make_float2(vx, vy);
}

// ---------------- launch ----------------
extern "C" void kernel_launch(void* const* d_in, const int* in_sizes, int n_in,
                              void* d_out, int out_size) {
    const float* x  = (const float*)d_in[0];
    const float* W  = (const float*)d_in[1];
    const float* a  = (const float*)d_in[2];
    const int*   ei = (const int*)d_in[3];
    float* out = (float*)d_out;

    (void)in_sizes; (void)n_in; (void)out_size;

    // Fork: side stream runs the entire edge pipeline (hist/scan/scores/csr),
    // which no longer depends on the gemm (scores come from x @ (W@a)).
    cudaStream_t s2;
    cudaEvent_t e1, e2;
    cudaStreamCreateWithFlags(&s2, cudaStreamNonBlocking);
    cudaEventCreateWithFlags(&e1, cudaEventDisableTiming);
    cudaEventCreateWithFlags(&e2, cudaEventDisableTiming);

    cudaEventRecord(e1, 0);
    cudaStreamWaitEvent(s2, e1, 0);

    k_init<<<(N_NODES + 255) / 256, 256, 0, s2>>>();
    k_hist_rank<<<(N_EDGES / 4 + 255) / 256, 256, 0, s2>>>(ei);
    k_scan_a<<<SCAN_BLOCKS, 256, 0, s2>>>();

    k_gemm<<<(N_NODES + GB_NODES - 1) / GB_NODES, GB_THREADS>>>(x, W);  // 4th launch (ncu)

    k_scan_b_u<<<1, 256, 0, s2>>>(W, a);
    k_scan_c<<<SCAN_BLOCKS, 256, 0, s2>>>();
    k_sx<<<(N_NODES * 32 + 255) / 256, 256, 0, s2>>>(x);
    k_csr<<<(N_EDGES + 255) / 256, 256, 0, s2>>>(ei);

    cudaEventRecord(e2, s2);
    cudaStreamWaitEvent(0, e2, 0);

    k_gather<<<(N_NODES * 32 + 255) / 256, 256>>>(out);
}

// round 12
// speedup vs baseline: 1.7718x; 1.0058x over previous
#include <cuda_runtime.h>
#include <cuda_fp16.h>
#include <math.h>

#define N_NODES 50000
#define IN_F    256
#define OUT_F   64
#define N_EDGES 1600000
#define ALPHA   0.2f

#define SCAN_BLOCKS 196   // 196*256 = 50176 >= 50000

// gemm tiling (R7 config): 128 nodes x 64 f per block, 256 threads, 4n x 8f per thread
#define GB_NODES 128
#define GB_THREADS 256
#define KCHUNK 64
#define XS_ROW 65
#define WT_ROW 48

typedef unsigned long long ull;

// ---------------- scratch (static device globals; no allocation) ----------------
__device__ __align__(16) __half g_hh[(size_t)N_NODES * OUT_F]; // 6.4 MB (fp16 h)
__device__ float g_s1[N_NODES];
__device__ float g_s2[N_NODES];
__device__ int   g_count[N_NODES];
__device__ int   g_rowstart[N_NODES + 1];
__device__ int   g_blocksum[SCAN_BLOCKS];
__device__ int   g_blockoff[SCAN_BLOCKS];
__device__ __align__(16) int g_rank[N_EDGES];                  // 6.4 MB
__device__ float g_u1[IN_F];
__device__ float g_u2[IN_F];
__device__ __align__(16) ull g_csr[N_EDGES];                   // 12.8 MB packed (dst, w)

// ---------------- zero histogram ----------------
__global__ void k_init() {
    int idx = blockIdx.x * blockDim.x + threadIdx.x;
    if (idx < N_NODES) g_count[idx] = 0;
}

// ---------------- histogram of src + per-edge rank ----------------
__global__ __launch_bounds__(256) void k_hist_rank(const int* __restrict__ ei) {
    int t = blockIdx.x * blockDim.x + threadIdx.x;
    if (t >= N_EDGES / 4) return;
    int4 v = ((const int4*)ei)[t];
    int4 r;
    r.x = atomicAdd(&g_count[v.x], 1);
    r.y = atomicAdd(&g_count[v.y], 1);
    r.z = atomicAdd(&g_count[v.z], 1);
    r.w = atomicAdd(&g_count[v.w], 1);
    ((int4*)g_rank)[t] = r;
}

// ---------------- u1 = W@a1, u2 = W@a2 (1 block, 256 threads) ----------------
__global__ __launch_bounds__(256) void k_u(const float* __restrict__ W,
                                           const float* __restrict__ a) {
    int t = threadIdx.x;
    float u1 = 0.f, u2 = 0.f;
    const float* wrow = W + (size_t)t * OUT_F;
    #pragma unroll 8
    for (int f = 0; f < OUT_F; f++) {
        float wv = wrow[f];
        u1 = fmaf(wv, __ldg(a + f), u1);
        u2 = fmaf(wv, __ldg(a + OUT_F + f), u2);
    }
    g_u1[t] = u1;
    g_u2[t] = u2;
}

// ---------------- scan stage A: per-block sums ----------------
__global__ __launch_bounds__(256) void k_scan_a() {
    __shared__ int sh[256];
    int i = blockIdx.x * 256 + threadIdx.x;
    sh[threadIdx.x] = (i < N_NODES) ? g_count[i] : 0;
    __syncthreads();
    for (int o = 128; o > 0; o >>= 1) {
        if (threadIdx.x < o) sh[threadIdx.x] += sh[threadIdx.x + o];
        __syncthreads();
    }
    if (threadIdx.x == 0) g_blocksum[blockIdx.x] = sh[0];
}

// ---------------- scan stage B ----------------
__global__ __launch_bounds__(256) void k_scan_b() {
    __shared__ int sh[256];
    int t = threadIdx.x;
    sh[t] = (t < SCAN_BLOCKS) ? g_blocksum[t] : 0;
    __syncthreads();
    #pragma unroll
    for (int o = 1; o < 256; o <<= 1) {
        int v = 0;
        if (t >= o) v = sh[t - o];
        __syncthreads();
        sh[t] += v;
        __syncthreads();
    }
    if (t < SCAN_BLOCKS) g_blockoff[t] = (t == 0) ? 0 : sh[t - 1];
    if (t == 0) g_rowstart[N_NODES] = N_EDGES;
}

// ---------------- scan stage C: block-local exclusive scan -> rowstart ----------------
__global__ __launch_bounds__(256) void k_scan_c() {
    __shared__ int sh[256];
    int t = threadIdx.x;
    int i = blockIdx.x * 256 + t;
    int cnt = (i < N_NODES) ? g_count[i] : 0;
    sh[t] = cnt;
    __syncthreads();
    #pragma unroll
    for (int o = 1; o < 256; o <<= 1) {
        int v = 0;
        if (t >= o) v = sh[t - o];
        __syncthreads();
        sh[t] += v;
        __syncthreads();
    }
    if (i < N_NODES) g_rowstart[i] = g_blockoff[blockIdx.x] + sh[t] - cnt;
}

// ---------------- scores from x: s1 = x@u1, s2 = x@u2 (one warp per node) --------
__global__ __launch_bounds__(256) void k_sx(const float* __restrict__ x) {
    int warp = (blockIdx.x * blockDim.x + threadIdx.x) >> 5;
    int lane = threadIdx.x & 31;
    if (warp >= N_NODES) return;
    const float4* xr = (const float4*)(x + (size_t)warp * IN_F);
    float4 xa = __ldg(xr + lane * 2);
    float4 xb = __ldg(xr + lane * 2 + 1);
    float4 ua = *(const float4*)(g_u1 + lane * 8);
    float4 ub = *(const float4*)(g_u1 + lane * 8 + 4);
    float4 va = *(const float4*)(g_u2 + lane * 8);
    float4 vb = *(const float4*)(g_u2 + lane * 8 + 4);
    float s1 = xa.x * ua.x + xa.y * ua.y + xa.z * ua.z + xa.w * ua.w
             + xb.x * ub.x + xb.y * ub.y + xb.z * ub.z + xb.w * ub.w;
    float s2 = xa.x * va.x + xa.y * va.y + xa.z * va.z + xa.w * va.w
             + xb.x * vb.x + xb.y * vb.y + xb.z * vb.z + xb.w * vb.w;
    #pragma unroll
    for (int o = 16; o; o >>= 1) {
        s1 += __shfl_xor_sync(0xFFFFFFFFu, s1, o);
        s2 += __shfl_xor_sync(0xFFFFFFFFu, s2, o);
    }
    if (lane == 0) { g_s1[warp] = s1; g_s2[warp] = s2; }
}

// ---------------- h = x @ W (R7 tiling), stored as fp16 ----------------
__global__ __launch_bounds__(GB_THREADS, 3) void k_gemm(const float* __restrict__ x,
                                                        const float* __restrict__ W) {
    __shared__ float xs[GB_NODES * XS_ROW];
    __shared__ __align__(16) ull Wt[KCHUNK * WT_ROW];

    const int tid = threadIdx.x;
    const int tx = tid & 7;
    const int ty = tid >> 3;
    const int f0 = tx * 8;
    const int n0 = ty * 4;
    const int nodeBase = blockIdx.x * GB_NODES;

    ull acc[4][4];
    #pragma unroll
    for (int j = 0; j < 4; j++)
        #pragma unroll
        for (int p = 0; p < 4; p++) acc[j][p] = 0ull;

    for (int kc = 0; kc < IN_F; kc += KCHUNK) {
        __syncthreads();
        #pragma unroll
        for (int i = 0; i < (GB_NODES * KCHUNK / 4) / GB_THREADS; i++) {
            int flat = i * GB_THREADS + tid;
            int node = flat >> 4;
            int kv   = flat & 15;
            int gn   = nodeBase + node;
            float4 v = make_float4(0.f, 0.f, 0.f, 0.f);
            if (gn < N_NODES)
                v = *(const float4*)(x + (size_t)gn * IN_F + kc + kv * 4);
            float* dst = &xs[node * XS_ROW + kv * 4];
            dst[0] = v.x; dst[1] = v.y; dst[2] = v.z; dst[3] = v.w;
        }
        #pragma unroll
        for (int i = 0; i < (KCHUNK * OUT_F / 4) / GB_THREADS; i++) {
            int flat = i * GB_THREADS + tid;
            int kr = flat >> 4;
            int kv = flat & 15;
            float4 v = *(const float4*)(W + (size_t)(kc + kr) * OUT_F + kv * 4);
            *(ulonglong2*)&Wt[kr * WT_ROW + (kv >> 1) * 6 + (kv & 1) * 2] =
                *(ulonglong2*)&v;
        }
        __syncthreads();

        #pragma unroll 4
        for (int k = 0; k < KCHUNK; k++) {
            const ull* wrow = &Wt[k * WT_ROW + tx * 6];
            ull w0 = wrow[0], w1 = wrow[1], w2 = wrow[2], w3 = wrow[3];
            const float* xcol = &xs[n0 * XS_ROW + k];
            #pragma unroll
            for (int j = 0; j < 4; j++) {
                float xv = xcol[j * XS_ROW];
                ull xp;
                asm("mov.b64 %0, {%1, %1};" : "=l"(xp) : "r"(__float_as_uint(xv)));
                asm("fma.rn.f32x2 %0, %1, %2, %0;" : "+l"(acc[j][0]) : "l"(xp), "l"(w0));
                asm("fma.rn.f32x2 %0, %1, %2, %0;" : "+l"(acc[j][1]) : "l"(xp), "l"(w1));
                asm("fma.rn.f32x2 %0, %1, %2, %0;" : "+l"(acc[j][2]) : "l"(xp), "l"(w2));
                asm("fma.rn.f32x2 %0, %1, %2, %0;" : "+l"(acc[j][3]) : "l"(xp), "l"(w3));
            }
        }
    }

    // store h as fp16: 8 features = 4 half2 = one 16B store per node
    #pragma unroll
    for (int j = 0; j < 4; j++) {
        int gn = nodeBase + n0 + j;
        if (gn < N_NODES) {
            __half2 o[4];
            #pragma unroll
            for (int p = 0; p < 4; p++) {
                float lo = __uint_as_float((unsigned)acc[j][p]);
                float hi = __uint_as_float((unsigned)(acc[j][p] >> 32));
                o[p] = __floats2half2_rn(lo, hi);
            }
            *(float4*)(g_hh + (size_t)gn * OUT_F + f0) = *(float4*)o;
        }
    }
}

// ---------------- build CSR (atomic-free, rank precomputed) ----------------
__global__ __launch_bounds__(256) void k_csr(const int* __restrict__ ei) {
    int e = blockIdx.x * blockDim.x + threadIdx.x;
    if (e >= N_EDGES) return;
    int src = ei[e];
    int dst = ei[N_EDGES + e];
    float s  = __ldg(g_s1 + src) + __ldg(g_s2 + dst);
    float lr = s > 0.f ? s : ALPHA * s;
    float w  = expf(-lr);
    int pos = g_rowstart[src] + g_rank[e];
    g_csr[pos] = (ull)(unsigned)dst | ((ull)__float_as_uint(w) << 32);
}

// ---------------- gather per node (warp), fp16 h, fused divide+ELU ----------------
__global__ __launch_bounds__(256) void k_gather(float* __restrict__ out) {
    int warp = (blockIdx.x * blockDim.x + threadIdx.x) >> 5;
    int lane = threadIdx.x & 31;
    if (warp >= N_NODES) return;

    int s = g_rowstart[warp];
    int e = g_rowstart[warp + 1];

    float ax = 0.f, ay = 0.f, rs = 0.f;
    int i = s;

    #pragma unroll 1
    for (; i + 8 <= e; i += 8) {
        ull v[8];
        #pragma unroll
        for (int j = 0; j < 8; j++) v[j] = g_csr[i + j];
        unsigned hv[8];
        #pragma unroll
        for (int j = 0; j < 8; j++) {
            int d = (int)(unsigned)v[j];
            hv[j] = ((const unsigned*)(g_hh + (size_t)d * OUT_F))[lane];
        }
        #pragma unroll
        for (int j = 0; j < 8; j++) {
            float w = __uint_as_float((unsigned)(v[j] >> 32));
            float2 hf = __half22float2(*(__half2*)&hv[j]);
            rs += w;
            ax = fmaf(w, hf.x, ax);
            ay = fmaf(w, hf.y, ay);
        }
    }
    for (; i < e; i++) {
        ull v = g_csr[i];
        int   d = (int)(unsigned)v;
        float w = __uint_as_float((unsigned)(v >> 32));
        unsigned u = ((const unsigned*)(g_hh + (size_t)d * OUT_F))[lane];
        float2 hf = __half22float2(*(__half2*)&u);
        rs += w;
        ax = fmaf(w, hf.x, ax);
        ay = fmaf(w, hf.y, ay);
    }

    float inv = 1.f / rs;
    float vx = ax * inv;
    float vy = ay * inv;
    vx = vx > 0.f ? vx : expm1f(vx);
    vy = vy > 0.f ? vy : expm1f(vy);
    ((float2*)(out + (size_t)warp * OUT_F))[lane] = make_float2(vx, vy);
}

// ---------------- launch ----------------
extern "C" void kernel_launch(void* const* d_in, const int* in_sizes, int n_in,
                              void* d_out, int out_size) {
    const float* x  = (const float*)d_in[0];
    const float* W  = (const float*)d_in[1];
    const float* a  = (const float*)d_in[2];
    const int*   ei = (const int*)d_in[3];
    float* out = (float*)d_out;

    (void)in_sizes; (void)n_in; (void)out_size;

    // ONE side stream (two streams tripped the teardown memory check in R11).
    //   main: u -> sx -> [eS] -> gemm
    //   s2:   init -> hist_rank -> scan_a/b/c -> (wait eS) -> csr -> [e2]
    //   main: (wait e2) -> gather
    cudaStream_t s2;
    cudaEvent_t e1, e2, eS;
    cudaStreamCreateWithFlags(&s2, cudaStreamNonBlocking);
    cudaEventCreateWithFlags(&e1, cudaEventDisableTiming);
    cudaEventCreateWithFlags(&e2, cudaEventDisableTiming);
    cudaEventCreateWithFlags(&eS, cudaEventDisableTiming);

    cudaEventRecord(e1, 0);
    cudaStreamWaitEvent(s2, e1, 0);

    k_init<<<(N_NODES + 255) / 256, 256, 0, s2>>>();
    k_hist_rank<<<(N_EDGES / 4 + 255) / 256, 256, 0, s2>>>(ei);

    k_u<<<1, 256>>>(W, a);
    k_sx<<<(N_NODES * 32 + 255) / 256, 256>>>(x);
    cudaEventRecord(eS, 0);

    k_scan_a<<<SCAN_BLOCKS, 256, 0, s2>>>();
    k_scan_b<<<1, 256, 0, s2>>>();
    k_scan_c<<<SCAN_BLOCKS, 256, 0, s2>>>();

    k_gemm<<<(N_NODES + GB_NODES - 1) / GB_NODES, GB_THREADS>>>(x, W);

    cudaStreamWaitEvent(s2, eS, 0);
    k_csr<<<(N_EDGES + 255) / 256, 256, 0, s2>>>(ei);

    cudaEventRecord(e2, s2);
    cudaStreamWaitEvent(0, e2, 0);
    k_gather<<<(N_NODES * 32 + 255) / 256, 256>>>(out);
}

// round 13
// speedup vs baseline: 1.8230x; 1.0289x over previous
#include <cuda_runtime.h>
#include <cuda_fp16.h>
#include <math.h>

#define N_NODES 50000
#define IN_F    256
#define OUT_F   64
#define N_EDGES 1600000
#define ALPHA   0.2f

#define SCAN_BLOCKS 196   // 196*256 = 50176 >= 50000

// gemm tiling: 128 nodes x 64 f per block, 256 threads, 4n x 8f per thread
#define GB_NODES 128
#define GB_THREADS 256
#define KCHUNK 64
#define XS_ROW 65
#define WT_ROW 48

typedef unsigned long long ull;

// ---------------- scratch (static device globals; no allocation) ----------------
__device__ __align__(16) __half g_hh[(size_t)N_NODES * OUT_F]; // 6.4 MB (fp16 h)
__device__ float g_s1[N_NODES];
__device__ float g_s2[N_NODES];
__device__ int   g_count[N_NODES];
__device__ int   g_rowstart[N_NODES + 1];
__device__ int   g_blocksum[SCAN_BLOCKS];
__device__ int   g_blockoff[SCAN_BLOCKS];
__device__ __align__(16) int g_rank[N_EDGES];                  // 6.4 MB
__device__ __align__(16) int g_csrd[N_EDGES];                  // 6.4 MB (dst only)

// ---------------- zero histogram ----------------
__global__ void k_init() {
    int idx = blockIdx.x * blockDim.x + threadIdx.x;
    if (idx < N_NODES) g_count[idx] = 0;
}

// ---------------- histogram of src + per-edge rank ----------------
__global__ __launch_bounds__(256) void k_hist_rank(const int* __restrict__ ei) {
    int t = blockIdx.x * blockDim.x + threadIdx.x;
    if (t >= N_EDGES / 4) return;
    int4 v = ((const int4*)ei)[t];
    int4 r;
    r.x = atomicAdd(&g_count[v.x], 1);
    r.y = atomicAdd(&g_count[v.y], 1);
    r.z = atomicAdd(&g_count[v.z], 1);
    r.w = atomicAdd(&g_count[v.w], 1);
    ((int4*)g_rank)[t] = r;
}

// ---------------- scan stage A: per-block sums ----------------
__global__ __launch_bounds__(256) void k_scan_a() {
    __shared__ int sh[256];
    int i = blockIdx.x * 256 + threadIdx.x;
    sh[threadIdx.x] = (i < N_NODES) ? g_count[i] : 0;
    __syncthreads();
    for (int o = 128; o > 0; o >>= 1) {
        if (threadIdx.x < o) sh[threadIdx.x] += sh[threadIdx.x + o];
        __syncthreads();
    }
    if (threadIdx.x == 0) g_blocksum[blockIdx.x] = sh[0];
}

// ---------------- scan stage B ----------------
__global__ __launch_bounds__(256) void k_scan_b() {
    __shared__ int sh[256];
    int t = threadIdx.x;
    sh[t] = (t < SCAN_BLOCKS) ? g_blocksum[t] : 0;
    __syncthreads();
    #pragma unroll
    for (int o = 1; o < 256; o <<= 1) {
        int v = 0;
        if (t >= o) v = sh[t - o];
        __syncthreads();
        sh[t] += v;
        __syncthreads();
    }
    if (t < SCAN_BLOCKS) g_blockoff[t] = (t == 0) ? 0 : sh[t - 1];
    if (t == 0) g_rowstart[N_NODES] = N_EDGES;
}

// ---------------- scan stage C: block-local exclusive scan -> rowstart ----------------
__global__ __launch_bounds__(256) void k_scan_c() {
    __shared__ int sh[256];
    int t = threadIdx.x;
    int i = blockIdx.x * 256 + t;
    int cnt = (i < N_NODES) ? g_count[i] : 0;
    sh[t] = cnt;
    __syncthreads();
    #pragma unroll
    for (int o = 1; o < 256; o <<= 1) {
        int v = 0;
        if (t >= o) v = sh[t - o];
        __syncthreads();
        sh[t] += v;
        __syncthreads();
    }
    if (i < N_NODES) g_rowstart[i] = g_blockoff[blockIdx.x] + sh[t] - cnt;
}

// ---------------- h = x @ W (fp16 store) + fused scores s1/s2 ----------------
__global__ __launch_bounds__(GB_THREADS, 3) void k_gemm(const float* __restrict__ x,
                                                        const float* __restrict__ W,
                                                        const float* __restrict__ a) {
    __shared__ float xs[GB_NODES * XS_ROW];
    __shared__ __align__(16) ull Wt[KCHUNK * WT_ROW];

    const int tid = threadIdx.x;
    const int tx = tid & 7;
    const int ty = tid >> 3;
    const int f0 = tx * 8;
    const int n0 = ty * 4;
    const int nodeBase = blockIdx.x * GB_NODES;

    ull acc[4][4];
    #pragma unroll
    for (int j = 0; j < 4; j++)
        #pragma unroll
        for (int p = 0; p < 4; p++) acc[j][p] = 0ull;

    for (int kc = 0; kc < IN_F; kc += KCHUNK) {
        __syncthreads();
        #pragma unroll
        for (int i = 0; i < (GB_NODES * KCHUNK / 4) / GB_THREADS; i++) {
            int flat = i * GB_THREADS + tid;
            int node = flat >> 4;
            int kv   = flat & 15;
            int gn   = nodeBase + node;
            float4 v = make_float4(0.f, 0.f, 0.f, 0.f);
            if (gn < N_NODES)
                v = *(const float4*)(x + (size_t)gn * IN_F + kc + kv * 4);
            float* dst = &xs[node * XS_ROW + kv * 4];
            dst[0] = v.x; dst[1] = v.y; dst[2] = v.z; dst[3] = v.w;
        }
        #pragma unroll
        for (int i = 0; i < (KCHUNK * OUT_F / 4) / GB_THREADS; i++) {
            int flat = i * GB_THREADS + tid;
            int kr = flat >> 4;
            int kv = flat & 15;
            float4 v = *(const float4*)(W + (size_t)(kc + kr) * OUT_F + kv * 4);
            *(ulonglong2*)&Wt[kr * WT_ROW + (kv >> 1) * 6 + (kv & 1) * 2] =
                *(ulonglong2*)&v;
        }
        __syncthreads();

        #pragma unroll 4
        for (int k = 0; k < KCHUNK; k++) {
            const ull* wrow = &Wt[k * WT_ROW + tx * 6];
            ull w0 = wrow[0], w1 = wrow[1], w2 = wrow[2], w3 = wrow[3];
            const float* xcol = &xs[n0 * XS_ROW + k];
            #pragma unroll
            for (int j = 0; j < 4; j++) {
                float xv = xcol[j * XS_ROW];
                ull xp;
                asm("mov.b64 %0, {%1, %1};" : "=l"(xp) : "r"(__float_as_uint(xv)));
                asm("fma.rn.f32x2 %0, %1, %2, %0;" : "+l"(acc[j][0]) : "l"(xp), "l"(w0));
                asm("fma.rn.f32x2 %0, %1, %2, %0;" : "+l"(acc[j][1]) : "l"(xp), "l"(w1));
                asm("fma.rn.f32x2 %0, %1, %2, %0;" : "+l"(acc[j][2]) : "l"(xp), "l"(w2));
                asm("fma.rn.f32x2 %0, %1, %2, %0;" : "+l"(acc[j][3]) : "l"(xp), "l"(w3));
            }
        }
    }

    // epilogue: fp16 h store + fused scores
    float a1[8], a2[8];
    #pragma unroll
    for (int i = 0; i < 8; i++) {
        a1[i] = __ldg(a + f0 + i);
        a2[i] = __ldg(a + OUT_F + f0 + i);
    }

    #pragma unroll
    for (int j = 0; j < 4; j++) {
        int gn = nodeBase + n0 + j;
        float hf[8];
        #pragma unroll
        for (int p = 0; p < 4; p++) {
            hf[2 * p]     = __uint_as_float((unsigned)acc[j][p]);
            hf[2 * p + 1] = __uint_as_float((unsigned)(acc[j][p] >> 32));
        }
        if (gn < N_NODES) {
            __half2 o[4];
            #pragma unroll
            for (int p = 0; p < 4; p++)
                o[p] = __floats2half2_rn(hf[2 * p], hf[2 * p + 1]);
            *(float4*)(g_hh + (size_t)gn * OUT_F + f0) = *(float4*)o;
        }
        float s1 = 0.f, s2 = 0.f;
        #pragma unroll
        for (int i = 0; i < 8; i++) {
            s1 = fmaf(hf[i], a1[i], s1);
            s2 = fmaf(hf[i], a2[i], s2);
        }
        #pragma unroll
        for (int o = 1; o < 8; o <<= 1) {
            s1 += __shfl_xor_sync(0xFFFFFFFFu, s1, o);
            s2 += __shfl_xor_sync(0xFFFFFFFFu, s2, o);
        }
        if (tx == 0 && gn < N_NODES) {
            g_s1[gn] = s1;
            g_s2[gn] = s2;
        }
    }
}

// ---------------- build CSR (dst only, atomic-free; no score dependency) ----------
__global__ __launch_bounds__(256) void k_csr(const int* __restrict__ ei) {
    int e = blockIdx.x * blockDim.x + threadIdx.x;
    if (e >= N_EDGES) return;
    int src = ei[e];
    int dst = ei[N_EDGES + e];
    g_csrd[g_rowstart[src] + g_rank[e]] = dst;
}

// ---------------- gather per node (warp): weight computed in-flight --------------
__global__ __launch_bounds__(256) void k_gather(float* __restrict__ out) {
    int warp = (blockIdx.x * blockDim.x + threadIdx.x) >> 5;
    int lane = threadIdx.x & 31;
    if (warp >= N_NODES) return;

    int s = g_rowstart[warp];
    int e = g_rowstart[warp + 1];
    float s1 = __ldg(g_s1 + warp);

    float ax = 0.f, ay = 0.f, rs = 0.f;
    int i = s;

    #pragma unroll 1
    for (; i + 8 <= e; i += 8) {
        int d[8];
        #pragma unroll
        for (int j = 0; j < 8; j++) d[j] = __ldg(g_csrd + i + j);   // warp-broadcast
        float sc[8];
        unsigned hv[8];
        #pragma unroll
        for (int j = 0; j < 8; j++) {
            sc[j] = __ldg(g_s2 + d[j]);                              // warp-broadcast
            hv[j] = ((const unsigned*)(g_hh + (size_t)d[j] * OUT_F))[lane];
        }
        #pragma unroll
        for (int j = 0; j < 8; j++) {
            float t  = s1 + sc[j];
            float lr = t > 0.f ? t : ALPHA * t;
            float w  = expf(-lr);
            float2 hf = __half22float2(*(__half2*)&hv[j]);
            rs += w;
            ax = fmaf(w, hf.x, ax);
            ay = fmaf(w, hf.y, ay);
        }
    }
    for (; i < e; i++) {
        int d = __ldg(g_csrd + i);
        float t  = s1 + __ldg(g_s2 + d);
        float lr = t > 0.f ? t : ALPHA * t;
        float w  = expf(-lr);
        unsigned u = ((const unsigned*)(g_hh + (size_t)d * OUT_F))[lane];
        float2 hf = __half22float2(*(__half2*)&u);
        rs += w;
        ax = fmaf(w, hf.x, ax);
        ay = fmaf(w, hf.y, ay);
    }

    float inv = 1.f / rs;
    float vx = ax * inv;
    float vy = ay * inv;
    vx = vx > 0.f ? vx : expm1f(vx);
    vy = vy > 0.f ? vy : expm1f(vy);
    ((float2*)(out + (size_t)warp * OUT_F))[lane] = make_float2(vx, vy);
}

// ---------------- launch ----------------
extern "C" void kernel_launch(void* const* d_in, const int* in_sizes, int n_in,
                              void* d_out, int out_size) {
    const float* x  = (const float*)d_in[0];
    const float* W  = (const float*)d_in[1];
    const float* a  = (const float*)d_in[2];
    const int*   ei = (const int*)d_in[3];
    float* out = (float*)d_out;

    (void)in_sizes; (void)n_in; (void)out_size;

    // main: gemm (h + scores). side s2: init -> hist_rank -> scans -> csr_lite.
    // gather waits on both.
    cudaStream_t s2;
    cudaEvent_t e1, e2;
    cudaStreamCreateWithFlags(&s2, cudaStreamNonBlocking);
    cudaEventCreateWithFlags(&e1, cudaEventDisableTiming);
    cudaEventCreateWithFlags(&e2, cudaEventDisableTiming);

    cudaEventRecord(e1, 0);
    cudaStreamWaitEvent(s2, e1, 0);

    k_init<<<(N_NODES + 255) / 256, 256, 0, s2>>>();
    k_hist_rank<<<(N_EDGES / 4 + 255) / 256, 256, 0, s2>>>(ei);
    k_scan_a<<<SCAN_BLOCKS, 256, 0, s2>>>();

    k_gemm<<<(N_NODES + GB_NODES - 1) / GB_NODES, GB_THREADS>>>(x, W, a);  // 4th launch

    k_scan_b<<<1, 256, 0, s2>>>();
    k_scan_c<<<SCAN_BLOCKS, 256, 0, s2>>>();
    k_csr<<<(N_EDGES + 255) / 256, 256, 0, s2>>>(ei);

    cudaEventRecord(e2, s2);
    cudaStreamWaitEvent(0, e2, 0);
    k_gather<<<(N_NODES * 32 + 255) / 256, 256>>>(out);
}

// round 14
// speedup vs baseline: 1.9015x; 1.0431x over previous
#include <cuda_runtime.h>
#include <cuda_fp16.h>
#include <math.h>

#define N_NODES 50000
#define IN_F    256
#define OUT_F   64
#define N_EDGES 1600000
#define ALPHA   0.2f

#define SCAN_BLOCKS 196   // 196*256 = 50176 >= 50000

// gemm tiling: 128 nodes x 64 f per block, 256 threads, 4n x 8f per thread
#define GB_NODES 128
#define GB_THREADS 256
#define KCHUNK 64
#define XS_ROW 65
#define WT_ROW 48

typedef unsigned long long ull;

// ---------------- scratch (static device globals; no allocation) ----------------
__device__ __align__(16) __half g_hh[(size_t)N_NODES * OUT_F]; // 6.4 MB (fp16 h)
__device__ float g_s1[N_NODES];
__device__ float g_s2[N_NODES];
__device__ int   g_count[N_NODES];
__device__ int   g_rowstart[N_NODES + 1];
__device__ int   g_blocksum[SCAN_BLOCKS];
__device__ __align__(16) int g_rank[N_EDGES];                  // 6.4 MB
__device__ __align__(16) ull g_csr[N_EDGES];                   // 12.8 MB packed (dst, w)

// ---------------- zero histogram ----------------
__global__ void k_init() {
    int idx = blockIdx.x * blockDim.x + threadIdx.x;
    if (idx < N_NODES) g_count[idx] = 0;
}

// ---------------- histogram of src + per-edge rank ----------------
__global__ __launch_bounds__(256) void k_hist_rank(const int* __restrict__ ei) {
    int t = blockIdx.x * blockDim.x + threadIdx.x;
    if (t >= N_EDGES / 4) return;
    int4 v = ((const int4*)ei)[t];
    int4 r;
    r.x = atomicAdd(&g_count[v.x], 1);
    r.y = atomicAdd(&g_count[v.y], 1);
    r.z = atomicAdd(&g_count[v.z], 1);
    r.w = atomicAdd(&g_count[v.w], 1);
    ((int4*)g_rank)[t] = r;
}

// ---------------- scan stage A: per-block sums ----------------
__global__ __launch_bounds__(256) void k_scan_a() {
    __shared__ int sh[256];
    int i = blockIdx.x * 256 + threadIdx.x;
    sh[threadIdx.x] = (i < N_NODES) ? g_count[i] : 0;
    __syncthreads();
    for (int o = 128; o > 0; o >>= 1) {
        if (threadIdx.x < o) sh[threadIdx.x] += sh[threadIdx.x + o];
        __syncthreads();
    }
    if (threadIdx.x == 0) g_blocksum[blockIdx.x] = sh[0];
}

// ---------------- scan stage C2: self-service global offset + local scan ----------
__global__ __launch_bounds__(256) void k_scan_c2() {
    __shared__ int sh[256];
    __shared__ int s_base;
    int t = threadIdx.x;

    // phase 1: base = sum of blocksums for blocks < blockIdx.x
    int partial = 0;
    if (t < SCAN_BLOCKS && t < blockIdx.x) partial = g_blocksum[t];
    sh[t] = partial;
    __syncthreads();
    for (int o = 128; o > 0; o >>= 1) {
        if (t < o) sh[t] += sh[t + o];
        __syncthreads();
    }
    if (t == 0) s_base = sh[0];
    __syncthreads();

    // phase 2: local inclusive scan of counts
    int i = blockIdx.x * 256 + t;
    int cnt = (i < N_NODES) ? g_count[i] : 0;
    sh[t] = cnt;
    __syncthreads();
    #pragma unroll
    for (int o = 1; o < 256; o <<= 1) {
        int v = 0;
        if (t >= o) v = sh[t - o];
        __syncthreads();
        sh[t] += v;
        __syncthreads();
    }
    if (i < N_NODES) g_rowstart[i] = s_base + sh[t] - cnt;
    if (blockIdx.x == SCAN_BLOCKS - 1 && t == 0) g_rowstart[N_NODES] = N_EDGES;
}

// ---------------- h = x @ W (fp16 store) + fused scores s1/s2 ----------------
__global__ __launch_bounds__(GB_THREADS, 3) void k_gemm(const float* __restrict__ x,
                                                        const float* __restrict__ W,
                                                        const float* __restrict__ a) {
    __shared__ float xs[GB_NODES * XS_ROW];
    __shared__ __align__(16) ull Wt[KCHUNK * WT_ROW];

    const int tid = threadIdx.x;
    const int tx = tid & 7;
    const int ty = tid >> 3;
    const int f0 = tx * 8;
    const int n0 = ty * 4;
    const int nodeBase = blockIdx.x * GB_NODES;

    ull acc[4][4];
    #pragma unroll
    for (int j = 0; j < 4; j++)
        #pragma unroll
        for (int p = 0; p < 4; p++) acc[j][p] = 0ull;

    for (int kc = 0; kc < IN_F; kc += KCHUNK) {
        __syncthreads();
        #pragma unroll
        for (int i = 0; i < (GB_NODES * KCHUNK / 4) / GB_THREADS; i++) {
            int flat = i * GB_THREADS + tid;
            int node = flat >> 4;
            int kv   = flat & 15;
            int gn   = nodeBase + node;
            float4 v = make_float4(0.f, 0.f, 0.f, 0.f);
            if (gn < N_NODES)
                v = *(const float4*)(x + (size_t)gn * IN_F + kc + kv * 4);
            float* dst = &xs[node * XS_ROW + kv * 4];
            dst[0] = v.x; dst[1] = v.y; dst[2] = v.z; dst[3] = v.w;
        }
        #pragma unroll
        for (int i = 0; i < (KCHUNK * OUT_F / 4) / GB_THREADS; i++) {
            int flat = i * GB_THREADS + tid;
            int kr = flat >> 4;
            int kv = flat & 15;
            float4 v = *(const float4*)(W + (size_t)(kc + kr) * OUT_F + kv * 4);
            *(ulonglong2*)&Wt[kr * WT_ROW + (kv >> 1) * 6 + (kv & 1) * 2] =
                *(ulonglong2*)&v;
        }
        __syncthreads();

        #pragma unroll 4
        for (int k = 0; k < KCHUNK; k++) {
            const ull* wrow = &Wt[k * WT_ROW + tx * 6];
            ull w0 = wrow[0], w1 = wrow[1], w2 = wrow[2], w3 = wrow[3];
            const float* xcol = &xs[n0 * XS_ROW + k];
            #pragma unroll
            for (int j = 0; j < 4; j++) {
                float xv = xcol[j * XS_ROW];
                ull xp;
                asm("mov.b64 %0, {%1, %1};" : "=l"(xp) : "r"(__float_as_uint(xv)));
                asm("fma.rn.f32x2 %0, %1, %2, %0;" : "+l"(acc[j][0]) : "l"(xp), "l"(w0));
                asm("fma.rn.f32x2 %0, %1, %2, %0;" : "+l"(acc[j][1]) : "l"(xp), "l"(w1));
                asm("fma.rn.f32x2 %0, %1, %2, %0;" : "+l"(acc[j][2]) : "l"(xp), "l"(w2));
                asm("fma.rn.f32x2 %0, %1, %2, %0;" : "+l"(acc[j][3]) : "l"(xp), "l"(w3));
            }
        }
    }

    // epilogue: fp16 h store + fused scores
    float a1[8], a2[8];
    #pragma unroll
    for (int i = 0; i < 8; i++) {
        a1[i] = __ldg(a + f0 + i);
        a2[i] = __ldg(a + OUT_F + f0 + i);
    }

    #pragma unroll
    for (int j = 0; j < 4; j++) {
        int gn = nodeBase + n0 + j;
        float hf[8];
        #pragma unroll
        for (int p = 0; p < 4; p++) {
            hf[2 * p]     = __uint_as_float((unsigned)acc[j][p]);
            hf[2 * p + 1] = __uint_as_float((unsigned)(acc[j][p] >> 32));
        }
        if (gn < N_NODES) {
            __half2 o[4];
            #pragma unroll
            for (int p = 0; p < 4; p++)
                o[p] = __floats2half2_rn(hf[2 * p], hf[2 * p + 1]);
            *(float4*)(g_hh + (size_t)gn * OUT_F + f0) = *(float4*)o;
        }
        float s1 = 0.f, s2 = 0.f;
        #pragma unroll
        for (int i = 0; i < 8; i++) {
            s1 = fmaf(hf[i], a1[i], s1);
            s2 = fmaf(hf[i], a2[i], s2);
        }
        #pragma unroll
        for (int o = 1; o < 8; o <<= 1) {
            s1 += __shfl_xor_sync(0xFFFFFFFFu, s1, o);
            s2 += __shfl_xor_sync(0xFFFFFFFFu, s2, o);
        }
        if (tx == 0 && gn < N_NODES) {
            g_s1[gn] = s1;
            g_s2[gn] = s2;
        }
    }
}

// ---------------- build CSR: packed (dst, w), atomic-free ----------------
__global__ __launch_bounds__(256) void k_csr(const int* __restrict__ ei) {
    int e = blockIdx.x * blockDim.x + threadIdx.x;
    if (e >= N_EDGES) return;
    int src = ei[e];
    int dst = ei[N_EDGES + e];
    float s  = __ldg(g_s1 + src) + __ldg(g_s2 + dst);
    float lr = s > 0.f ? s : ALPHA * s;
    float w  = expf(-lr);
    int pos = g_rowstart[src] + g_rank[e];
    g_csr[pos] = (ull)(unsigned)dst | ((ull)__float_as_uint(w) << 32);
}

// ---------------- gather per node (warp), fp16 h, fused divide+ELU ----------------
__global__ __launch_bounds__(256) void k_gather(float* __restrict__ out) {
    int warp = (blockIdx.x * blockDim.x + threadIdx.x) >> 5;
    int lane = threadIdx.x & 31;
    if (warp >= N_NODES) return;

    int s = g_rowstart[warp];
    int e = g_rowstart[warp + 1];

    float ax = 0.f, ay = 0.f, rs = 0.f;
    int i = s;

    #pragma unroll 1
    for (; i + 8 <= e; i += 8) {
        ull v[8];
        #pragma unroll
        for (int j = 0; j < 8; j++) v[j] = g_csr[i + j];
        unsigned hv[8];
        #pragma unroll
        for (int j = 0; j < 8; j++) {
            int d = (int)(unsigned)v[j];
            hv[j] = ((const unsigned*)(g_hh + (size_t)d * OUT_F))[lane];
        }
        #pragma unroll
        for (int j = 0; j < 8; j++) {
            float w = __uint_as_float((unsigned)(v[j] >> 32));
            float2 hf = __half22float2(*(__half2*)&hv[j]);
            rs += w;
            ax = fmaf(w, hf.x, ax);
            ay = fmaf(w, hf.y, ay);
        }
    }
    for (; i < e; i++) {
        ull v = g_csr[i];
        int   d = (int)(unsigned)v;
        float w = __uint_as_float((unsigned)(v >> 32));
        unsigned u = ((const unsigned*)(g_hh + (size_t)d * OUT_F))[lane];
        float2 hf = __half22float2(*(__half2*)&u);
        rs += w;
        ax = fmaf(w, hf.x, ax);
        ay = fmaf(w, hf.y, ay);
    }

    float inv = 1.f / rs;
    float vx = ax * inv;
    float vy = ay * inv;
    vx = vx > 0.f ? vx : expm1f(vx);
    vy = vy > 0.f ? vy : expm1f(vy);
    ((float2*)(out + (size_t)warp * OUT_F))[lane] = make_float2(vx, vy);
}

// ---------------- launch ----------------
extern "C" void kernel_launch(void* const* d_in, const int* in_sizes, int n_in,
                              void* d_out, int out_size) {
    const float* x  = (const float*)d_in[0];
    const float* W  = (const float*)d_in[1];
    const float* a  = (const float*)d_in[2];
    const int*   ei = (const int*)d_in[3];
    float* out = (float*)d_out;

    (void)in_sizes; (void)n_in; (void)out_size;

    // side s2: init -> hist_rank -> scan_a -> scan_c2 (finishes ~22us, hidden)
    // main:   gemm (h fp16 + scores) -> [join side] csr (packed w) -> gather
    cudaStream_t s2;
    cudaEvent_t e1, e2;
    cudaStreamCreateWithFlags(&s2, cudaStreamNonBlocking);
    cudaEventCreateWithFlags(&e1, cudaEventDisableTiming);
    cudaEventCreateWithFlags(&e2, cudaEventDisableTiming);

    cudaEventRecord(e1, 0);
    cudaStreamWaitEvent(s2, e1, 0);

    k_init<<<(N_NODES + 255) / 256, 256, 0, s2>>>();
    k_hist_rank<<<(N_EDGES / 4 + 255) / 256, 256, 0, s2>>>(ei);
    k_scan_a<<<SCAN_BLOCKS, 256, 0, s2>>>();

    k_gemm<<<(N_NODES + GB_NODES - 1) / GB_NODES, GB_THREADS>>>(x, W, a);  // 4th launch

    k_scan_c2<<<SCAN_BLOCKS, 256, 0, s2>>>();

    cudaEventRecord(e2, s2);
    cudaStreamWaitEvent(0, e2, 0);

    k_csr<<<(N_EDGES + 255) / 256, 256>>>(ei);
    k_gather<<<(N_NODES * 32 + 255) / 256, 256>>>(out);
}